// round 9
// baseline (speedup 1.0000x reference)
#include <cuda_runtime.h>
#include <cuda_bf16.h>
#include <cstdint>
#include <math.h>

// Problem constants
#define BATCH 2
#define SEQ   2048
#define DMODEL 1024
#define NHEAD 16
#define HDIM  64
#define HALF  32
#define MROWS (BATCH * SEQ)   // 4096

// Scratch (static device globals — allocation-free rule)
__device__ float g_q[MROWS * DMODEL];
__device__ float g_k[MROWS * DMODEL];
__device__ float g_v[MROWS * DMODEL];
__device__ float g_attn[MROWS * DMODEL];

__device__ __forceinline__ float tf32r(float x) {
    float r;
    asm("cvt.rna.tf32.f32 %0, %1;" : "=f"(r) : "f"(x));
    return r;
}

__device__ __forceinline__ void mma_tf32(float c[4], uint32_t a0, uint32_t a1,
                                         uint32_t a2, uint32_t a3,
                                         uint32_t b0, uint32_t b1) {
    asm volatile(
        "mma.sync.aligned.m16n8k8.row.col.f32.tf32.tf32.f32 "
        "{%0,%1,%2,%3}, {%4,%5,%6,%7}, {%8,%9}, {%0,%1,%2,%3};"
        : "+f"(c[0]), "+f"(c[1]), "+f"(c[2]), "+f"(c[3])
        : "r"(a0), "r"(a1), "r"(a2), "r"(a3), "r"(b0), "r"(b1));
}

// ---------------------------------------------------------------------------
// tf32 mma.sync GEMM: C = A @ W^T + bias, optional RoPE.
// CTA 64x128, 256 threads / 8 warps (2Mx4N), warp tile 32x32.
// 2 CTAs/SM (independent barrier domains) for latency hiding.
// K chunks of 32, double-buffered smem, stride-36 conflict-free layout.
// ---------------------------------------------------------------------------
#define BM 64
#define BN 128
#define KC 32
#define NT (DMODEL / KC)       // 32
#define AST 36                 // floats per smem row
#define ATILEF (BM * AST)      // 2304 floats
#define BTILEF (BN * AST)      // 4608 floats
#define SMEM_DYN ((2 * ATILEF + 2 * BTILEF) * 4)   // 55296 bytes

__global__ void __launch_bounds__(256, 2)
gemm_tf32_kernel(const float* __restrict__ A,
                 const float* __restrict__ W,
                 const float* __restrict__ bias,
                 float* __restrict__ C,
                 const float* __restrict__ cosb,
                 const float* __restrict__ sinb,
                 int applyRope)
{
    extern __shared__ float ds[];
    float* aT[2] = { ds,              ds + ATILEF };
    float* bT[2] = { ds + 2 * ATILEF, ds + 2 * ATILEF + BTILEF };

    const int tid = threadIdx.x;
    const int wid = tid >> 5;          // 0..7
    const int lid = tid & 31;
    const int wm = (wid & 1) * 32;     // warp M offset
    const int wn = (wid >> 1) * 32;    // warp N offset
    const int m0 = blockIdx.y * BM;
    const int n0 = blockIdx.x * BN;

    // staging: A 512 float4-slots (2/thread), B 1024 slots (4/thread)
    const int ra0_ = tid >> 3;             // A row, slot tid       (0..31)
    const int ra1_ = (tid + 256) >> 3;     // A row, slot tid+256   (32..63)
    const int c4_  = (tid & 7) * 4;        // col 0..28

    const float* Abase = A + (size_t)m0 * DMODEL;
    const float* Wbase = W + (size_t)n0 * DMODEL;

    float4 ar[2], br[4];

    #define LOADT(kt) do {                                                     \
        ar[0] = *(const float4*)(Abase + (size_t)ra0_ * DMODEL + (kt) * KC + c4_); \
        ar[1] = *(const float4*)(Abase + (size_t)ra1_ * DMODEL + (kt) * KC + c4_); \
        _Pragma("unroll")                                                      \
        for (int _i = 0; _i < 4; _i++) {                                       \
            int _r = (tid + _i * 256) >> 3;                                    \
            br[_i] = *(const float4*)(Wbase + (size_t)_r * DMODEL + (kt) * KC + c4_); \
        }                                                                      \
    } while (0)

    #define STST(buf) do {                                                     \
        _Pragma("unroll")                                                      \
        for (int _i = 0; _i < 2; _i++) {                                       \
            const int _r = _i ? ra1_ : ra0_;                                   \
            float4 _a = ar[_i];                                                \
            _a.x = tf32r(_a.x); _a.y = tf32r(_a.y);                            \
            _a.z = tf32r(_a.z); _a.w = tf32r(_a.w);                            \
            *(float4*)(aT[buf] + _r * AST + c4_) = _a;                         \
        }                                                                      \
        _Pragma("unroll")                                                      \
        for (int _i = 0; _i < 4; _i++) {                                       \
            int _r = (tid + _i * 256) >> 3;                                    \
            float4 _b = br[_i];                                                \
            _b.x = tf32r(_b.x); _b.y = tf32r(_b.y);                            \
            _b.z = tf32r(_b.z); _b.w = tf32r(_b.w);                            \
            *(float4*)(bT[buf] + _r * AST + c4_) = _b;                         \
        }                                                                      \
    } while (0)

    float acc[2][4][4];
    #pragma unroll
    for (int i = 0; i < 2; i++)
        #pragma unroll
        for (int j = 0; j < 4; j++)
            #pragma unroll
            for (int r = 0; r < 4; r++) acc[i][j][r] = 0.f;

    const int lm = lid >> 2;          // 0..7
    const int lk = lid & 3;           // 0..3

    LOADT(0);
    STST(0);
    __syncthreads();
    LOADT(1);

    for (int kt = 0; kt < NT; kt++) {
        const int cur = kt & 1;
        if (kt + 1 < NT) STST(cur ^ 1);
        if (kt + 2 < NT) LOADT(kt + 2);

        const float* sa = aT[cur] + (wm + lm) * AST + lk;
        const float* sb = bT[cur] + (wn + lm) * AST + lk;
        #pragma unroll
        for (int ks = 0; ks < 4; ks++) {
            uint32_t af[2][4], bf[4][2];
            #pragma unroll
            for (int mf = 0; mf < 2; mf++) {
                af[mf][0] = __float_as_uint(sa[(mf * 16    ) * AST + ks * 8    ]);
                af[mf][1] = __float_as_uint(sa[(mf * 16 + 8) * AST + ks * 8    ]);
                af[mf][2] = __float_as_uint(sa[(mf * 16    ) * AST + ks * 8 + 4]);
                af[mf][3] = __float_as_uint(sa[(mf * 16 + 8) * AST + ks * 8 + 4]);
            }
            #pragma unroll
            for (int nf = 0; nf < 4; nf++) {
                bf[nf][0] = __float_as_uint(sb[(nf * 8) * AST + ks * 8    ]);
                bf[nf][1] = __float_as_uint(sb[(nf * 8) * AST + ks * 8 + 4]);
            }
            #pragma unroll
            for (int mf = 0; mf < 2; mf++)
                #pragma unroll
                for (int nf = 0; nf < 4; nf++)
                    mma_tf32(acc[mf][nf], af[mf][0], af[mf][1], af[mf][2], af[mf][3],
                             bf[nf][0], bf[nf][1]);
        }
        __syncthreads();
    }

    // epilogue: bias (+ RoPE), direct STG
    const int ln = (lid & 3) * 2;
    #pragma unroll
    for (int mf = 0; mf < 2; mf++) {
        #pragma unroll
        for (int half = 0; half < 2; half++) {
            const int m = m0 + wm + mf * 16 + lm + half * 8;
            const int spos = m & (SEQ - 1);
            float* crow = C + (size_t)m * DMODEL;
            #pragma unroll
            for (int nf = 0; nf < 4; nf++) {
                const int n = n0 + wn + nf * 8 + ln;
                float v0 = acc[mf][nf][half * 2 + 0] + bias[n];
                float v1 = acc[mf][nf][half * 2 + 1] + bias[n + 1];
                if (applyRope) {
                    const int fi = (n & (HDIM - 1)) >> 1;
                    const float cc = cosb[spos * HALF + fi];
                    const float ss = sinb[spos * HALF + fi];
                    const float r0 = v0 * cc - v1 * ss;
                    const float r1 = v0 * ss + v1 * cc;
                    v0 = r0; v1 = r1;
                }
                float2 st; st.x = v0; st.y = v1;
                *(float2*)(crow + n) = st;
            }
        }
    }
}

// ---------------------------------------------------------------------------
// Tensor-core flash attention (tf32 mma.sync) — unchanged from R7.
// CTA = 128 queries of one (b,h); 8 warps x 16 rows; KV tiles of 64.
// ---------------------------------------------------------------------------
#define KST 68
#define VST 72
#define PST 68
#define ATTN_SMEM ((64 * KST + 64 * VST + 128 * PST) * 4)   // 70656 bytes

__global__ void __launch_bounds__(256, 1)
attn_mma_kernel()
{
    extern __shared__ float smf[];
    float* kt = smf;
    float* vt = kt + 64 * KST;
    float* pt = vt + 64 * VST;

    const int b  = blockIdx.z;
    const int h  = blockIdx.y;
    const int q0 = blockIdx.x * 128;
    const int tid = threadIdx.x;
    const int w   = tid >> 5;
    const int lid = tid & 31;
    const int lm = lid >> 2;
    const int lk = lid & 3;
    const int ln = lk * 2;

    const float* qg = g_q + ((size_t)(b * SEQ + q0) * DMODEL + h * HDIM);
    #pragma unroll
    for (int i = 0; i < 8; i++) {
        int idx = tid + i * 256;
        int row = idx >> 4;
        int c4  = (idx & 15) * 4;
        float4 v = *(const float4*)(qg + (size_t)row * DMODEL + c4);
        v.x = tf32r(v.x * 0.125f); v.y = tf32r(v.y * 0.125f);
        v.z = tf32r(v.z * 0.125f); v.w = tf32r(v.w * 0.125f);
        *(float4*)(pt + row * PST + c4) = v;
    }
    __syncthreads();

    uint32_t aq[8][4];
    {
        const float* qs = pt + (w * 16 + lm) * PST + lk;
        #pragma unroll
        for (int ks = 0; ks < 8; ks++) {
            aq[ks][0] = __float_as_uint(qs[ks * 8]);
            aq[ks][1] = __float_as_uint(qs[8 * PST + ks * 8]);
            aq[ks][2] = __float_as_uint(qs[ks * 8 + 4]);
            aq[ks][3] = __float_as_uint(qs[8 * PST + ks * 8 + 4]);
        }
    }

    float m0 = -1e30f, m1 = -1e30f, l0 = 0.f, l1 = 0.f;
    float oacc[8][4];
    #pragma unroll
    for (int nt = 0; nt < 8; nt++)
        #pragma unroll
        for (int r = 0; r < 4; r++) oacc[nt][r] = 0.f;

    const float* kg = g_k + ((size_t)(b * SEQ) * DMODEL + h * HDIM);
    const float* vg = g_v + ((size_t)(b * SEQ) * DMODEL + h * HDIM);

    const int ntiles = q0 / 64 + 2;
    for (int t = 0; t < ntiles; t++) {
        const int kv0 = t * 64;
        #pragma unroll
        for (int i = 0; i < 4; i++) {
            int idx = tid + i * 256;
            int row = idx >> 4;
            int c4  = (idx & 15) * 4;
            float4 kk = *(const float4*)(kg + (size_t)(kv0 + row) * DMODEL + c4);
            kk.x = tf32r(kk.x); kk.y = tf32r(kk.y);
            kk.z = tf32r(kk.z); kk.w = tf32r(kk.w);
            *(float4*)(kt + row * KST + c4) = kk;
            float4 vv = *(const float4*)(vg + (size_t)(kv0 + row) * DMODEL + c4);
            vv.x = tf32r(vv.x); vv.y = tf32r(vv.y);
            vv.z = tf32r(vv.z); vv.w = tf32r(vv.w);
            *(float4*)(vt + row * VST + c4) = vv;
        }
        __syncthreads();

        const bool active = !(w < 4 && t == ntiles - 1);
        if (active) {
            float sacc[8][4];
            #pragma unroll
            for (int nt = 0; nt < 8; nt++)
                #pragma unroll
                for (int r = 0; r < 4; r++) sacc[nt][r] = 0.f;

            #pragma unroll
            for (int ks = 0; ks < 8; ks++) {
                #pragma unroll
                for (int nt = 0; nt < 8; nt++) {
                    uint32_t b0 = __float_as_uint(kt[(nt * 8 + lm) * KST + ks * 8 + lk]);
                    uint32_t b1 = __float_as_uint(kt[(nt * 8 + lm) * KST + ks * 8 + lk + 4]);
                    mma_tf32(sacc[nt], aq[ks][0], aq[ks][1], aq[ks][2], aq[ks][3], b0, b1);
                }
            }

            if (t >= ntiles - 2) {
                const int rel0 = q0 + w * 16 + lm - kv0;
                const int rel1 = rel0 + 8;
                #pragma unroll
                for (int nt = 0; nt < 8; nt++) {
                    const int c0 = nt * 8 + ln;
                    if (c0     > rel0) sacc[nt][0] = -1e30f;
                    if (c0 + 1 > rel0) sacc[nt][1] = -1e30f;
                    if (c0     > rel1) sacc[nt][2] = -1e30f;
                    if (c0 + 1 > rel1) sacc[nt][3] = -1e30f;
                }
            }

            float rm0 = -1e30f, rm1 = -1e30f;
            #pragma unroll
            for (int nt = 0; nt < 8; nt++) {
                rm0 = fmaxf(rm0, fmaxf(sacc[nt][0], sacc[nt][1]));
                rm1 = fmaxf(rm1, fmaxf(sacc[nt][2], sacc[nt][3]));
            }
            rm0 = fmaxf(rm0, __shfl_xor_sync(0xffffffffu, rm0, 1));
            rm0 = fmaxf(rm0, __shfl_xor_sync(0xffffffffu, rm0, 2));
            rm1 = fmaxf(rm1, __shfl_xor_sync(0xffffffffu, rm1, 1));
            rm1 = fmaxf(rm1, __shfl_xor_sync(0xffffffffu, rm1, 2));

            const float mn0 = fmaxf(m0, rm0);
            const float mn1 = fmaxf(m1, rm1);
            const float sc0 = __expf(m0 - mn0);
            const float sc1 = __expf(m1 - mn1);
            m0 = mn0; m1 = mn1;
            l0 *= sc0; l1 *= sc1;
            #pragma unroll
            for (int nt = 0; nt < 8; nt++) {
                oacc[nt][0] *= sc0; oacc[nt][1] *= sc0;
                oacc[nt][2] *= sc1; oacc[nt][3] *= sc1;
            }

            float* pw = pt + (w * 16 + lm) * PST;
            #pragma unroll
            for (int nt = 0; nt < 8; nt++) {
                const float p0 = __expf(sacc[nt][0] - m0);
                const float p1 = __expf(sacc[nt][1] - m0);
                const float p2 = __expf(sacc[nt][2] - m1);
                const float p3 = __expf(sacc[nt][3] - m1);
                l0 += p0 + p1;
                l1 += p2 + p3;
                *(float2*)(pw + nt * 8 + ln)           = make_float2(p0, p1);
                *(float2*)(pw + 8 * PST + nt * 8 + ln) = make_float2(p2, p3);
            }
            __syncwarp();

            const float* pa = pt + (w * 16 + lm) * PST + lk;
            #pragma unroll
            for (int ks = 0; ks < 8; ks++) {
                const uint32_t a0 = __float_as_uint(pa[ks * 8]);
                const uint32_t a1 = __float_as_uint(pa[8 * PST + ks * 8]);
                const uint32_t a2 = __float_as_uint(pa[ks * 8 + 4]);
                const uint32_t a3 = __float_as_uint(pa[8 * PST + ks * 8 + 4]);
                #pragma unroll
                for (int nt = 0; nt < 8; nt++) {
                    uint32_t b0 = __float_as_uint(vt[(ks * 8 + lk) * VST + nt * 8 + lm]);
                    uint32_t b1 = __float_as_uint(vt[(ks * 8 + lk + 4) * VST + nt * 8 + lm]);
                    mma_tf32(oacc[nt], a0, a1, a2, a3, b0, b1);
                }
            }
        }
        __syncthreads();
    }

    l0 += __shfl_xor_sync(0xffffffffu, l0, 1);
    l0 += __shfl_xor_sync(0xffffffffu, l0, 2);
    l1 += __shfl_xor_sync(0xffffffffu, l1, 1);
    l1 += __shfl_xor_sync(0xffffffffu, l1, 2);
    const float inv0 = 1.f / l0;
    const float inv1 = 1.f / l1;

    float* og = g_attn + ((size_t)(b * SEQ + q0 + w * 16 + lm) * DMODEL + h * HDIM);
    #pragma unroll
    for (int nt = 0; nt < 8; nt++) {
        *(float2*)(og + nt * 8 + ln) =
            make_float2(oacc[nt][0] * inv0, oacc[nt][1] * inv0);
        *(float2*)(og + 8 * DMODEL + nt * 8 + ln) =
            make_float2(oacc[nt][2] * inv1, oacc[nt][3] * inv1);
    }
}

// ---------------------------------------------------------------------------
// Launch
// ---------------------------------------------------------------------------
extern "C" void kernel_launch(void* const* d_in, const int* in_sizes, int n_in,
                              void* d_out, int out_size)
{
    (void)in_sizes; (void)n_in; (void)out_size;
    const float* x       = (const float*)d_in[0];
    const float* pos_cos = (const float*)d_in[1];
    const float* pos_sin = (const float*)d_in[2];
    const float* wq_w    = (const float*)d_in[3];
    const float* wq_b    = (const float*)d_in[4];
    const float* wk_w    = (const float*)d_in[5];
    const float* wk_b    = (const float*)d_in[6];
    const float* wv_w    = (const float*)d_in[7];
    const float* wv_b    = (const float*)d_in[8];
    const float* wo_w    = (const float*)d_in[9];
    const float* wo_b    = (const float*)d_in[10];
    float* out = (float*)d_out;

    float *qp, *kp, *vp, *ap;
    cudaGetSymbolAddress((void**)&qp, g_q);
    cudaGetSymbolAddress((void**)&kp, g_k);
    cudaGetSymbolAddress((void**)&vp, g_v);
    cudaGetSymbolAddress((void**)&ap, g_attn);

    cudaFuncSetAttribute(gemm_tf32_kernel,
                         cudaFuncAttributeMaxDynamicSharedMemorySize, SMEM_DYN);
    cudaFuncSetAttribute(attn_mma_kernel,
                         cudaFuncAttributeMaxDynamicSharedMemorySize, ATTN_SMEM);

    dim3 gg(DMODEL / BN, MROWS / BM);   // (8, 64)
    gemm_tf32_kernel<<<gg, 256, SMEM_DYN>>>(x, wq_w, wq_b, qp, pos_cos, pos_sin, 1);
    gemm_tf32_kernel<<<gg, 256, SMEM_DYN>>>(x, wk_w, wk_b, kp, pos_cos, pos_sin, 1);
    gemm_tf32_kernel<<<gg, 256, SMEM_DYN>>>(x, wv_w, wv_b, vp, pos_cos, pos_sin, 0);

    dim3 ga(SEQ / 128, NHEAD, BATCH);   // (16, 16, 2)
    attn_mma_kernel<<<ga, 256, ATTN_SMEM>>>();

    gemm_tf32_kernel<<<gg, 256, SMEM_DYN>>>(ap, wo_w, wo_b, out, pos_cos, pos_sin, 0);
}

// round 10
// speedup vs baseline: 2.1221x; 2.1221x over previous
#include <cuda_runtime.h>
#include <cuda_fp16.h>
#include <cstdint>
#include <math.h>

// Problem constants
#define BATCH 2
#define SEQ   2048
#define DMODEL 1024
#define NHEAD 16
#define HDIM  64
#define HALF  32
#define MROWS (BATCH * SEQ)   // 4096

// Scratch (static device globals — allocation-free rule)
__device__ float g_q[MROWS * DMODEL];
__device__ float g_k[MROWS * DMODEL];
__device__ float g_v[MROWS * DMODEL];
__device__ float g_attn[MROWS * DMODEL];

__device__ __forceinline__ uint32_t pack2(float a, float b) {
    __half2 h = __floats2half2_rn(a, b);   // low = a, high = b
    return *reinterpret_cast<uint32_t*>(&h);
}

__device__ __forceinline__ void mma_f16(float c[4], uint32_t a0, uint32_t a1,
                                        uint32_t a2, uint32_t a3,
                                        uint32_t b0, uint32_t b1) {
    asm volatile(
        "mma.sync.aligned.m16n8k16.row.col.f32.f16.f16.f32 "
        "{%0,%1,%2,%3}, {%4,%5,%6,%7}, {%8,%9}, {%0,%1,%2,%3};"
        : "+f"(c[0]), "+f"(c[1]), "+f"(c[2]), "+f"(c[3])
        : "r"(a0), "r"(a1), "r"(a2), "r"(a3), "r"(b0), "r"(b1));
}

// ---------------------------------------------------------------------------
// fp16 mma.sync GEMM: C = A @ W^T + bias, optional RoPE (fp32 accumulate).
// CTA 128x128, 256 thr / 8 warps (2Mx4N), warp tile 64x32.
// K chunks of 32; smem tiles: 128 rows x 16 data words (32 halves), stride 20
// words -> conflict-free m16n8k16 fragment loads. Double buffered.
// ---------------------------------------------------------------------------
#define BM 128
#define BN 128
#define KC 32
#define NT (DMODEL / KC)       // 32
#define GST 20                 // words per smem row
#define GTILEW (128 * GST)     // words per tile (2560)
#define SMEM_DYN (4 * GTILEW * 4)   // 40960 bytes

__global__ void __launch_bounds__(256)
gemm_f16_kernel(const float* __restrict__ A,
                const float* __restrict__ W,
                const float* __restrict__ bias,
                float* __restrict__ C,
                const float* __restrict__ cosb,
                const float* __restrict__ sinb,
                int applyRope)
{
    extern __shared__ uint32_t su[];
    uint32_t* aT[2] = { su,              su + GTILEW };
    uint32_t* bT[2] = { su + 2 * GTILEW, su + 3 * GTILEW };

    const int tid = threadIdx.x;
    const int wid = tid >> 5;
    const int lid = tid & 31;
    const int wm = (wid & 1) * 64;
    const int wn = (wid >> 1) * 32;
    const int m0 = blockIdx.y * BM;
    const int n0 = blockIdx.x * BN;

    // staging: 1024 float4 slots per operand (row = slot>>3, c4 = (slot&7)*4)
    const float* Abase = A + (size_t)m0 * DMODEL;
    const float* Wbase = W + (size_t)n0 * DMODEL;

    float4 ar[4], br[4];

    #define LOADT(kt) do {                                                     \
        _Pragma("unroll")                                                      \
        for (int _i = 0; _i < 4; _i++) {                                       \
            int _s = tid + _i * 256;                                           \
            int _r = _s >> 3, _c = (_s & 7) * 4;                               \
            ar[_i] = *(const float4*)(Abase + (size_t)_r * DMODEL + (kt) * KC + _c); \
            br[_i] = *(const float4*)(Wbase + (size_t)_r * DMODEL + (kt) * KC + _c); \
        }                                                                      \
    } while (0)

    #define STST(buf) do {                                                     \
        _Pragma("unroll")                                                      \
        for (int _i = 0; _i < 4; _i++) {                                       \
            int _s = tid + _i * 256;                                           \
            int _r = _s >> 3, _c = (_s & 7) * 4;                               \
            uint2 _pa; _pa.x = pack2(ar[_i].x, ar[_i].y);                      \
            _pa.y = pack2(ar[_i].z, ar[_i].w);                                 \
            *(uint2*)(aT[buf] + _r * GST + _c / 2) = _pa;                      \
            uint2 _pb; _pb.x = pack2(br[_i].x, br[_i].y);                      \
            _pb.y = pack2(br[_i].z, br[_i].w);                                 \
            *(uint2*)(bT[buf] + _r * GST + _c / 2) = _pb;                      \
        }                                                                      \
    } while (0)

    float acc[4][4][4];
    #pragma unroll
    for (int i = 0; i < 4; i++)
        #pragma unroll
        for (int j = 0; j < 4; j++)
            #pragma unroll
            for (int r = 0; r < 4; r++) acc[i][j][r] = 0.f;

    const int lm = lid >> 2;          // 0..7
    const int lk = lid & 3;           // 0..3

    LOADT(0);
    STST(0);
    __syncthreads();
    LOADT(1);

    for (int kt = 0; kt < NT; kt++) {
        const int cur = kt & 1;
        if (kt + 1 < NT) STST(cur ^ 1);
        if (kt + 2 < NT) LOADT(kt + 2);

        const uint32_t* sa = aT[cur] + (wm + lm) * GST + lk;
        const uint32_t* sb = bT[cur] + (wn + lm) * GST + lk;
        #pragma unroll
        for (int ks = 0; ks < 2; ks++) {       // KC/16
            uint32_t af[4][4], bf[4][2];
            #pragma unroll
            for (int mf = 0; mf < 4; mf++) {
                af[mf][0] = sa[(mf * 16    ) * GST + ks * 8    ];
                af[mf][1] = sa[(mf * 16 + 8) * GST + ks * 8    ];
                af[mf][2] = sa[(mf * 16    ) * GST + ks * 8 + 4];
                af[mf][3] = sa[(mf * 16 + 8) * GST + ks * 8 + 4];
            }
            #pragma unroll
            for (int nf = 0; nf < 4; nf++) {
                bf[nf][0] = sb[(nf * 8) * GST + ks * 8    ];
                bf[nf][1] = sb[(nf * 8) * GST + ks * 8 + 4];
            }
            #pragma unroll
            for (int mf = 0; mf < 4; mf++)
                #pragma unroll
                for (int nf = 0; nf < 4; nf++)
                    mma_f16(acc[mf][nf], af[mf][0], af[mf][1], af[mf][2], af[mf][3],
                            bf[nf][0], bf[nf][1]);
        }
        __syncthreads();
    }

    // epilogue: bias (+ RoPE), direct STG
    const int ln = lk * 2;
    #pragma unroll
    for (int mf = 0; mf < 4; mf++) {
        #pragma unroll
        for (int half = 0; half < 2; half++) {
            const int m = m0 + wm + mf * 16 + lm + half * 8;
            const int spos = m & (SEQ - 1);
            float* crow = C + (size_t)m * DMODEL;
            #pragma unroll
            for (int nf = 0; nf < 4; nf++) {
                const int n = n0 + wn + nf * 8 + ln;
                float v0 = acc[mf][nf][half * 2 + 0] + bias[n];
                float v1 = acc[mf][nf][half * 2 + 1] + bias[n + 1];
                if (applyRope) {
                    const int fi = (n & (HDIM - 1)) >> 1;
                    const float cc = cosb[spos * HALF + fi];
                    const float ss = sinb[spos * HALF + fi];
                    const float r0 = v0 * cc - v1 * ss;
                    const float r1 = v0 * ss + v1 * cc;
                    v0 = r0; v1 = r1;
                }
                float2 st; st.x = v0; st.y = v1;
                *(float2*)(crow + n) = st;
            }
        }
    }
}

// ---------------------------------------------------------------------------
// fp16 tensor-core flash attention.
// CTA = 128 queries of one (b,h); 8 warps x 16 rows; KV tiles of 64.
// kt: [key][d] halves (QK B-operand); vt: [d][key] halves (PV B-operand,
// transposed during staging); pt: Q then per-warp P, [q][key/d] halves.
// All word strides 36 -> conflict-free fragment LDS.
// ---------------------------------------------------------------------------
#define ASTW 36
#define KTW (64 * ASTW)      // 2304 words
#define VTW (64 * ASTW)      // 2304 words
#define PTW (128 * ASTW)     // 4608 words
#define ATTN_SMEM ((KTW + VTW + PTW) * 4)   // 36864 bytes

__global__ void __launch_bounds__(256)
attn_mma_kernel()
{
    extern __shared__ uint32_t su[];
    uint32_t* kt = su;
    uint32_t* vt = kt + KTW;
    uint32_t* pt = vt + VTW;

    const int b  = blockIdx.z;
    const int h  = blockIdx.y;
    const int q0 = ((int)gridDim.x - 1 - (int)blockIdx.x) * 128;  // heavy first
    const int tid = threadIdx.x;
    const int w   = tid >> 5;
    const int lid = tid & 31;
    const int lm = lid >> 2;
    const int lk = lid & 3;
    const int ln = lk * 2;

    // ---- stage Q (x 1/8, fp16) into pt ----
    const float* qg = g_q + ((size_t)(b * SEQ + q0) * DMODEL + h * HDIM);
    #pragma unroll
    for (int i = 0; i < 8; i++) {
        int s = tid + i * 256;           // 2048 slots = 128 rows x 16 float4
        int row = s >> 4;
        int c4  = (s & 15) * 4;
        float4 v = *(const float4*)(qg + (size_t)row * DMODEL + c4);
        uint2 p;
        p.x = pack2(v.x * 0.125f, v.y * 0.125f);
        p.y = pack2(v.z * 0.125f, v.w * 0.125f);
        *(uint2*)(pt + row * ASTW + c4 / 2) = p;
    }
    __syncthreads();

    // preload Q A-fragments (persist across tiles)
    uint32_t aq[4][4];
    {
        const uint32_t* qs = pt + (w * 16 + lm) * ASTW + lk;
        #pragma unroll
        for (int ks = 0; ks < 4; ks++) {
            aq[ks][0] = qs[ks * 8];
            aq[ks][1] = qs[8 * ASTW + ks * 8];
            aq[ks][2] = qs[ks * 8 + 4];
            aq[ks][3] = qs[8 * ASTW + ks * 8 + 4];
        }
    }

    float m0 = -1e30f, m1 = -1e30f, l0 = 0.f, l1 = 0.f;
    float oacc[8][4];
    #pragma unroll
    for (int nt = 0; nt < 8; nt++)
        #pragma unroll
        for (int r = 0; r < 4; r++) oacc[nt][r] = 0.f;

    const float* kg = g_k + ((size_t)(b * SEQ) * DMODEL + h * HDIM);
    const float* vg = g_v + ((size_t)(b * SEQ) * DMODEL + h * HDIM);

    const int ntiles = q0 / 64 + 2;
    for (int t = 0; t < ntiles; t++) {
        const int kv0 = t * 64;
        // K: [key][d] fp16
        #pragma unroll
        for (int i = 0; i < 4; i++) {
            int s = tid + i * 256;       // 1024 slots = 64 rows x 16 float4
            int row = s >> 4;
            int c4  = (s & 15) * 4;
            float4 kk = *(const float4*)(kg + (size_t)(kv0 + row) * DMODEL + c4);
            uint2 p;
            p.x = pack2(kk.x, kk.y);
            p.y = pack2(kk.z, kk.w);
            *(uint2*)(kt + row * ASTW + c4 / 2) = p;
        }
        // V transposed: vt[d][keypair] with half2{V[2k][d], V[2k+1][d]}
        #pragma unroll
        for (int i = 0; i < 2; i++) {
            int task = tid + i * 256;    // 512 tasks = 32 keypairs x 16 d4-groups
            int kvp = task & 31;
            int d0  = (task >> 5) * 4;
            const float* r0p = vg + (size_t)(kv0 + 2 * kvp) * DMODEL + d0;
            const float* r1p = r0p + DMODEL;
            float4 va = *(const float4*)r0p;
            float4 vb = *(const float4*)r1p;
            vt[(d0 + 0) * ASTW + kvp] = pack2(va.x, vb.x);
            vt[(d0 + 1) * ASTW + kvp] = pack2(va.y, vb.y);
            vt[(d0 + 2) * ASTW + kvp] = pack2(va.z, vb.z);
            vt[(d0 + 3) * ASTW + kvp] = pack2(va.w, vb.w);
        }
        __syncthreads();

        const bool active = !(w < 4 && t == ntiles - 1);   // warp-uniform
        if (active) {
            // ---- S = Q K^T ----
            float sacc[8][4];
            #pragma unroll
            for (int nt = 0; nt < 8; nt++)
                #pragma unroll
                for (int r = 0; r < 4; r++) sacc[nt][r] = 0.f;

            #pragma unroll
            for (int ks = 0; ks < 4; ks++) {
                #pragma unroll
                for (int nt = 0; nt < 8; nt++) {
                    const uint32_t* kb = kt + (nt * 8 + lm) * ASTW + ks * 8 + lk;
                    mma_f16(sacc[nt], aq[ks][0], aq[ks][1], aq[ks][2], aq[ks][3],
                            kb[0], kb[4]);
                }
            }

            // ---- causal mask (last two tiles only) ----
            if (t >= ntiles - 2) {
                const int rel0 = q0 + w * 16 + lm - kv0;
                const int rel1 = rel0 + 8;
                #pragma unroll
                for (int nt = 0; nt < 8; nt++) {
                    const int c0 = nt * 8 + ln;
                    if (c0     > rel0) sacc[nt][0] = -1e30f;
                    if (c0 + 1 > rel0) sacc[nt][1] = -1e30f;
                    if (c0     > rel1) sacc[nt][2] = -1e30f;
                    if (c0 + 1 > rel1) sacc[nt][3] = -1e30f;
                }
            }

            // ---- online softmax ----
            float rm0 = -1e30f, rm1 = -1e30f;
            #pragma unroll
            for (int nt = 0; nt < 8; nt++) {
                rm0 = fmaxf(rm0, fmaxf(sacc[nt][0], sacc[nt][1]));
                rm1 = fmaxf(rm1, fmaxf(sacc[nt][2], sacc[nt][3]));
            }
            rm0 = fmaxf(rm0, __shfl_xor_sync(0xffffffffu, rm0, 1));
            rm0 = fmaxf(rm0, __shfl_xor_sync(0xffffffffu, rm0, 2));
            rm1 = fmaxf(rm1, __shfl_xor_sync(0xffffffffu, rm1, 1));
            rm1 = fmaxf(rm1, __shfl_xor_sync(0xffffffffu, rm1, 2));

            const float mn0 = fmaxf(m0, rm0);
            const float mn1 = fmaxf(m1, rm1);
            const float sc0 = __expf(m0 - mn0);
            const float sc1 = __expf(m1 - mn1);
            m0 = mn0; m1 = mn1;
            l0 *= sc0; l1 *= sc1;
            #pragma unroll
            for (int nt = 0; nt < 8; nt++) {
                oacc[nt][0] *= sc0; oacc[nt][1] *= sc0;
                oacc[nt][2] *= sc1; oacc[nt][3] *= sc1;
            }

            // ---- P = exp(S - m), stored fp16 to pt (own warp rows only) ----
            uint32_t* pw = pt + (w * 16 + lm) * ASTW;
            #pragma unroll
            for (int nt = 0; nt < 8; nt++) {
                const float p0 = __expf(sacc[nt][0] - m0);
                const float p1 = __expf(sacc[nt][1] - m0);
                const float p2 = __expf(sacc[nt][2] - m1);
                const float p3 = __expf(sacc[nt][3] - m1);
                l0 += p0 + p1;
                l1 += p2 + p3;
                pw[nt * 4 + lk]            = pack2(p0, p1);
                pw[8 * ASTW + nt * 4 + lk] = pack2(p2, p3);
            }
            __syncwarp();

            // ---- O += P V ----
            const uint32_t* pa = pt + (w * 16 + lm) * ASTW + lk;
            #pragma unroll
            for (int ks = 0; ks < 4; ks++) {
                const uint32_t a0 = pa[ks * 8];
                const uint32_t a1 = pa[8 * ASTW + ks * 8];
                const uint32_t a2 = pa[ks * 8 + 4];
                const uint32_t a3 = pa[8 * ASTW + ks * 8 + 4];
                #pragma unroll
                for (int nt = 0; nt < 8; nt++) {
                    const uint32_t* vb = vt + (nt * 8 + lm) * ASTW + ks * 8 + lk;
                    mma_f16(oacc[nt], a0, a1, a2, a3, vb[0], vb[4]);
                }
            }
        }
        __syncthreads();
    }

    // ---- finalize ----
    l0 += __shfl_xor_sync(0xffffffffu, l0, 1);
    l0 += __shfl_xor_sync(0xffffffffu, l0, 2);
    l1 += __shfl_xor_sync(0xffffffffu, l1, 1);
    l1 += __shfl_xor_sync(0xffffffffu, l1, 2);
    const float inv0 = 1.f / l0;
    const float inv1 = 1.f / l1;

    float* og = g_attn + ((size_t)(b * SEQ + q0 + w * 16 + lm) * DMODEL + h * HDIM);
    #pragma unroll
    for (int nt = 0; nt < 8; nt++) {
        *(float2*)(og + nt * 8 + ln) =
            make_float2(oacc[nt][0] * inv0, oacc[nt][1] * inv0);
        *(float2*)(og + 8 * DMODEL + nt * 8 + ln) =
            make_float2(oacc[nt][2] * inv1, oacc[nt][3] * inv1);
    }
}

// ---------------------------------------------------------------------------
// Launch
// ---------------------------------------------------------------------------
extern "C" void kernel_launch(void* const* d_in, const int* in_sizes, int n_in,
                              void* d_out, int out_size)
{
    (void)in_sizes; (void)n_in; (void)out_size;
    const float* x       = (const float*)d_in[0];
    const float* pos_cos = (const float*)d_in[1];
    const float* pos_sin = (const float*)d_in[2];
    const float* wq_w    = (const float*)d_in[3];
    const float* wq_b    = (const float*)d_in[4];
    const float* wk_w    = (const float*)d_in[5];
    const float* wk_b    = (const float*)d_in[6];
    const float* wv_w    = (const float*)d_in[7];
    const float* wv_b    = (const float*)d_in[8];
    const float* wo_w    = (const float*)d_in[9];
    const float* wo_b    = (const float*)d_in[10];
    float* out = (float*)d_out;

    float *qp, *kp, *vp, *ap;
    cudaGetSymbolAddress((void**)&qp, g_q);
    cudaGetSymbolAddress((void**)&kp, g_k);
    cudaGetSymbolAddress((void**)&vp, g_v);
    cudaGetSymbolAddress((void**)&ap, g_attn);

    cudaFuncSetAttribute(gemm_f16_kernel,
                         cudaFuncAttributeMaxDynamicSharedMemorySize, SMEM_DYN);
    cudaFuncSetAttribute(attn_mma_kernel,
                         cudaFuncAttributeMaxDynamicSharedMemorySize, ATTN_SMEM);

    dim3 gg(DMODEL / BN, MROWS / BM);   // (8, 32)
    gemm_f16_kernel<<<gg, 256, SMEM_DYN>>>(x, wq_w, wq_b, qp, pos_cos, pos_sin, 1);
    gemm_f16_kernel<<<gg, 256, SMEM_DYN>>>(x, wk_w, wk_b, kp, pos_cos, pos_sin, 1);
    gemm_f16_kernel<<<gg, 256, SMEM_DYN>>>(x, wv_w, wv_b, vp, pos_cos, pos_sin, 0);

    dim3 ga(SEQ / 128, NHEAD, BATCH);   // (16, 16, 2)
    attn_mma_kernel<<<ga, 256, ATTN_SMEM>>>();

    gemm_f16_kernel<<<gg, 256, SMEM_DYN>>>(ap, wo_w, wo_b, out, pos_cos, pos_sin, 0);
}

// round 12
// speedup vs baseline: 2.6969x; 1.2708x over previous
#include <cuda_runtime.h>
#include <cuda_fp16.h>
#include <cstdint>
#include <math.h>

// Problem constants
#define BATCH 2
#define SEQ   2048
#define DMODEL 1024
#define NHEAD 16
#define HDIM  64
#define HALF  32
#define MROWS (BATCH * SEQ)   // 4096

// Scratch (static device globals — allocation-free rule)
__device__ __half g_xh[MROWS * DMODEL];
__device__ __half g_whq[DMODEL * DMODEL];
__device__ __half g_whk[DMODEL * DMODEL];
__device__ __half g_whv[DMODEL * DMODEL];
__device__ __half g_who[DMODEL * DMODEL];
__device__ __half g_qh[MROWS * DMODEL];
__device__ __half g_kh[MROWS * DMODEL];
__device__ __half g_vh[MROWS * DMODEL];
__device__ __half g_ah[MROWS * DMODEL];

__device__ __forceinline__ uint32_t pack2(float a, float b) {
    __half2 h = __floats2half2_rn(a, b);
    return *reinterpret_cast<uint32_t*>(&h);
}

__device__ __forceinline__ void mma_f16(float c[4], uint32_t a0, uint32_t a1,
                                        uint32_t a2, uint32_t a3,
                                        uint32_t b0, uint32_t b1) {
    asm volatile(
        "mma.sync.aligned.m16n8k16.row.col.f32.f16.f16.f32 "
        "{%0,%1,%2,%3}, {%4,%5,%6,%7}, {%8,%9}, {%0,%1,%2,%3};"
        : "+f"(c[0]), "+f"(c[1]), "+f"(c[2]), "+f"(c[3])
        : "r"(a0), "r"(a1), "r"(a2), "r"(a3), "r"(b0), "r"(b1));
}

__device__ __forceinline__ uint32_t smem_u32(const void* p) {
    uint32_t a;
    asm("{ .reg .u64 t; cvta.to.shared.u64 t, %1; cvt.u32.u64 %0, t; }"
        : "=r"(a) : "l"(p));
    return a;
}

__device__ __forceinline__ void cp16(uint32_t dst, const void* src) {
    asm volatile("cp.async.cg.shared.global [%0], [%1], 16;"
                 :: "r"(dst), "l"(src));
}
#define CP_COMMIT() asm volatile("cp.async.commit_group;" ::: "memory")
#define CP_WAIT1()  asm volatile("cp.async.wait_group 1;"  ::: "memory")

// ---------------------------------------------------------------------------
// fp32 -> fp16 conversion (vectorized, grid-stride), optional scale.
// ---------------------------------------------------------------------------
__global__ void cvt_f2h_kernel(const float4* __restrict__ in,
                               uint2* __restrict__ out, int n4, float scale)
{
    for (int i = blockIdx.x * blockDim.x + threadIdx.x; i < n4;
         i += gridDim.x * blockDim.x) {
        float4 v = in[i];
        uint2 o;
        o.x = pack2(v.x * scale, v.y * scale);
        o.y = pack2(v.z * scale, v.w * scale);
        out[i] = o;
    }
}

// ---------------------------------------------------------------------------
// fp16 GEMM, cp.async 3-stage pipeline: C = A @ W^T + bias*bscale (+RoPE).
// A, W fp16; C fp16 (QKV) or fp32 (final). CTA 128x128, 8 warps, 64x32 tiles.
// ---------------------------------------------------------------------------
#define BM 128
#define BN 128
#define KC 32
#define NT (DMODEL / KC)       // 32
#define GST 20                 // words per smem row
#define GTILEW (128 * GST)
#define NSTAGE 3
#define SMEM_DYN (NSTAGE * 2 * GTILEW * 4)   // 61440 bytes

__global__ void __launch_bounds__(256, 2)
gemm_f16_kernel(const __half* __restrict__ A,
                const __half* __restrict__ W,
                const float* __restrict__ bias,
                float bscale,
                void* __restrict__ Cout,
                int outHalf,
                const float* __restrict__ cosb,
                const float* __restrict__ sinb,
                int applyRope)
{
    extern __shared__ uint32_t su[];
    const uint32_t sbase = smem_u32(su);

    const int tid = threadIdx.x;
    const int wid = tid >> 5;
    const int lid = tid & 31;
    const int wm = (wid & 1) * 64;
    const int wn = (wid >> 1) * 32;
    const int m0 = blockIdx.y * BM;
    const int n0 = blockIdx.x * BN;

    const __half* Abase = A + (size_t)m0 * DMODEL;
    const __half* Wbase = W + (size_t)n0 * DMODEL;

    // staging: per operand per chunk, 512 x 16B segs (4/row); 2 per thread
    const int r0_ = tid >> 2;            // rows 0..63
    const int r1_ = (tid + 256) >> 2;    // rows 64..127
    const int sg_ = (tid & 3) * 4;       // word col {0,4,8,12}

    #define CPLOAD(kt, stg) do {                                               \
        const __half* _as = Abase + (kt) * KC;                                 \
        const __half* _ws = Wbase + (kt) * KC;                                 \
        const uint32_t _ab = sbase + (2 * (stg)) * GTILEW * 4;                 \
        const uint32_t _bb = _ab + GTILEW * 4;                                 \
        cp16(_ab + (r0_ * GST + sg_) * 4, _as + (size_t)r0_ * DMODEL + sg_ * 2); \
        cp16(_ab + (r1_ * GST + sg_) * 4, _as + (size_t)r1_ * DMODEL + sg_ * 2); \
        cp16(_bb + (r0_ * GST + sg_) * 4, _ws + (size_t)r0_ * DMODEL + sg_ * 2); \
        cp16(_bb + (r1_ * GST + sg_) * 4, _ws + (size_t)r1_ * DMODEL + sg_ * 2); \
    } while (0)

    float acc[4][4][4];
    #pragma unroll
    for (int i = 0; i < 4; i++)
        #pragma unroll
        for (int j = 0; j < 4; j++)
            #pragma unroll
            for (int r = 0; r < 4; r++) acc[i][j][r] = 0.f;

    const int lm = lid >> 2;
    const int lk = lid & 3;

    CPLOAD(0, 0); CP_COMMIT();
    CPLOAD(1, 1); CP_COMMIT();

    for (int kt = 0; kt < NT; kt++) {
        CP_WAIT1();                 // own group for chunk kt complete
        __syncthreads();            // all threads' groups complete; prior reads done
        if (kt + 2 < NT) CPLOAD(kt + 2, (kt + 2) % NSTAGE);
        CP_COMMIT();

        const uint32_t* aS = su + (2 * (kt % NSTAGE)) * GTILEW;
        const uint32_t* bS = aS + GTILEW;
        const uint32_t* sa = aS + (wm + lm) * GST + lk;
        const uint32_t* sb = bS + (wn + lm) * GST + lk;
        #pragma unroll
        for (int ks = 0; ks < 2; ks++) {
            uint32_t af[4][4], bf[4][2];
            #pragma unroll
            for (int mf = 0; mf < 4; mf++) {
                af[mf][0] = sa[(mf * 16    ) * GST + ks * 8    ];
                af[mf][1] = sa[(mf * 16 + 8) * GST + ks * 8    ];
                af[mf][2] = sa[(mf * 16    ) * GST + ks * 8 + 4];
                af[mf][3] = sa[(mf * 16 + 8) * GST + ks * 8 + 4];
            }
            #pragma unroll
            for (int nf = 0; nf < 4; nf++) {
                bf[nf][0] = sb[(nf * 8) * GST + ks * 8    ];
                bf[nf][1] = sb[(nf * 8) * GST + ks * 8 + 4];
            }
            #pragma unroll
            for (int mf = 0; mf < 4; mf++)
                #pragma unroll
                for (int nf = 0; nf < 4; nf++)
                    mma_f16(acc[mf][nf], af[mf][0], af[mf][1], af[mf][2], af[mf][3],
                            bf[nf][0], bf[nf][1]);
        }
    }

    // epilogue: bias*bscale (+ RoPE), store fp16 or fp32
    const int ln = lk * 2;
    #pragma unroll
    for (int mf = 0; mf < 4; mf++) {
        #pragma unroll
        for (int half_ = 0; half_ < 2; half_++) {
            const int m = m0 + wm + mf * 16 + lm + half_ * 8;
            const int spos = m & (SEQ - 1);
            #pragma unroll
            for (int nf = 0; nf < 4; nf++) {
                const int n = n0 + wn + nf * 8 + ln;
                float v0 = acc[mf][nf][half_ * 2 + 0] + bias[n] * bscale;
                float v1 = acc[mf][nf][half_ * 2 + 1] + bias[n + 1] * bscale;
                if (applyRope) {
                    const int fi = (n & (HDIM - 1)) >> 1;
                    const float cc = cosb[spos * HALF + fi];
                    const float ss = sinb[spos * HALF + fi];
                    const float t0 = v0 * cc - v1 * ss;
                    const float t1 = v0 * ss + v1 * cc;
                    v0 = t0; v1 = t1;
                }
                if (outHalf) {
                    uint32_t* crow = (uint32_t*)Cout + (size_t)m * (DMODEL / 2);
                    crow[n / 2] = pack2(v0, v1);
                } else {
                    float* crow = (float*)Cout + (size_t)m * DMODEL;
                    float2 st; st.x = v0; st.y = v1;
                    *(float2*)(crow + n) = st;
                }
            }
        }
    }
}

// ---------------------------------------------------------------------------
// fp16 tensor-core flash attention (inputs/outputs fp16, fp32 accum).
// CTA = 128 queries of one (b,h); 8 warps x 16 rows; KV tiles of 64.
// 2 CTAs/SM. Smem word stride 36 -> conflict-free fragment LDS.
// Row layout: 32 data words (64 halves) + 4 pad.
// ---------------------------------------------------------------------------
#define ASTW 36
#define KTW (64 * ASTW)
#define VTW (64 * ASTW)
#define PTW (128 * ASTW)
#define ATTN_SMEM ((KTW + VTW + PTW) * 4)   // 36864 bytes

__global__ void __launch_bounds__(256, 2)
attn_mma_kernel()
{
    extern __shared__ uint32_t su[];
    uint32_t* kt = su;
    uint32_t* vt = kt + KTW;
    uint32_t* pt = vt + VTW;

    const int b  = blockIdx.z;
    const int h  = blockIdx.y;
    const int q0 = ((int)gridDim.x - 1 - (int)blockIdx.x) * 128;  // heavy first
    const int tid = threadIdx.x;
    const int w   = tid >> 5;
    const int lid = tid & 31;
    const int lm = lid >> 2;
    const int lk = lid & 3;
    const int ln = lk * 2;

    // ---- stage Q into pt: 128 rows x 8 segs (32 words/row) = 1024 segs ----
    const __half* qg = g_qh + ((size_t)(b * SEQ + q0) * DMODEL + h * HDIM);
    #pragma unroll
    for (int i = 0; i < 4; i++) {
        int s = tid + i * 256;
        int row = s >> 3;
        int sg  = (s & 7) * 4;
        uint4 v = *(const uint4*)(qg + (size_t)row * DMODEL + sg * 2);
        *(uint4*)(pt + row * ASTW + sg) = v;
    }
    __syncthreads();

    uint32_t aq[4][4];
    {
        const uint32_t* qs = pt + (w * 16 + lm) * ASTW + lk;
        #pragma unroll
        for (int ks = 0; ks < 4; ks++) {
            aq[ks][0] = qs[ks * 8];
            aq[ks][1] = qs[8 * ASTW + ks * 8];
            aq[ks][2] = qs[ks * 8 + 4];
            aq[ks][3] = qs[8 * ASTW + ks * 8 + 4];
        }
    }

    float m0 = -1e30f, m1 = -1e30f, l0 = 0.f, l1 = 0.f;
    float oacc[8][4];
    #pragma unroll
    for (int nt = 0; nt < 8; nt++)
        #pragma unroll
        for (int r = 0; r < 4; r++) oacc[nt][r] = 0.f;

    const __half* kg = g_kh + ((size_t)(b * SEQ) * DMODEL + h * HDIM);
    const __half* vg = g_vh + ((size_t)(b * SEQ) * DMODEL + h * HDIM);

    const int ntiles = q0 / 64 + 2;
    for (int t = 0; t < ntiles; t++) {
        const int kv0 = t * 64;
        // K tile: 64 rows x 8 segs = 512 segs
        #pragma unroll
        for (int i = 0; i < 2; i++) {
            int s = tid + i * 256;
            int row = s >> 3;
            int sg  = (s & 7) * 4;
            uint4 v = *(const uint4*)(kg + (size_t)(kv0 + row) * DMODEL + sg * 2);
            *(uint4*)(kt + row * ASTW + sg) = v;
        }
        // V tile transposed: vt[d][kvpair] = half2{V[2k][d], V[2k+1][d]}
        #pragma unroll
        for (int i = 0; i < 2; i++) {
            int task = tid + i * 256;    // 512 = 32 kvp x 16 d-groups
            int kvp = task & 31;
            int d0  = (task >> 5) * 4;
            const __half* e = vg + (size_t)(kv0 + 2 * kvp) * DMODEL + d0;
            uint2 we = *(const uint2*)e;
            uint2 wo = *(const uint2*)(e + DMODEL);
            vt[(d0 + 0) * ASTW + kvp] = __byte_perm(we.x, wo.x, 0x5410);
            vt[(d0 + 1) * ASTW + kvp] = __byte_perm(we.x, wo.x, 0x7632);
            vt[(d0 + 2) * ASTW + kvp] = __byte_perm(we.y, wo.y, 0x5410);
            vt[(d0 + 3) * ASTW + kvp] = __byte_perm(we.y, wo.y, 0x7632);
        }
        __syncthreads();

        const bool active = !(w < 4 && t == ntiles - 1);   // warp-uniform
        if (active) {
            // ---- S = Q K^T ----
            float sacc[8][4];
            #pragma unroll
            for (int nt = 0; nt < 8; nt++)
                #pragma unroll
                for (int r = 0; r < 4; r++) sacc[nt][r] = 0.f;

            #pragma unroll
            for (int ks = 0; ks < 4; ks++) {
                #pragma unroll
                for (int nt = 0; nt < 8; nt++) {
                    const uint32_t* kb = kt + (nt * 8 + lm) * ASTW + ks * 8 + lk;
                    mma_f16(sacc[nt], aq[ks][0], aq[ks][1], aq[ks][2], aq[ks][3],
                            kb[0], kb[4]);
                }
            }

            if (t >= ntiles - 2) {
                const int rel0 = q0 + w * 16 + lm - kv0;
                const int rel1 = rel0 + 8;
                #pragma unroll
                for (int nt = 0; nt < 8; nt++) {
                    const int c0 = nt * 8 + ln;
                    if (c0     > rel0) sacc[nt][0] = -1e30f;
                    if (c0 + 1 > rel0) sacc[nt][1] = -1e30f;
                    if (c0     > rel1) sacc[nt][2] = -1e30f;
                    if (c0 + 1 > rel1) sacc[nt][3] = -1e30f;
                }
            }

            float rm0 = -1e30f, rm1 = -1e30f;
            #pragma unroll
            for (int nt = 0; nt < 8; nt++) {
                rm0 = fmaxf(rm0, fmaxf(sacc[nt][0], sacc[nt][1]));
                rm1 = fmaxf(rm1, fmaxf(sacc[nt][2], sacc[nt][3]));
            }
            rm0 = fmaxf(rm0, __shfl_xor_sync(0xffffffffu, rm0, 1));
            rm0 = fmaxf(rm0, __shfl_xor_sync(0xffffffffu, rm0, 2));
            rm1 = fmaxf(rm1, __shfl_xor_sync(0xffffffffu, rm1, 1));
            rm1 = fmaxf(rm1, __shfl_xor_sync(0xffffffffu, rm1, 2));

            const float mn0 = fmaxf(m0, rm0);
            const float mn1 = fmaxf(m1, rm1);
            const float sc0 = __expf(m0 - mn0);
            const float sc1 = __expf(m1 - mn1);
            m0 = mn0; m1 = mn1;
            l0 *= sc0; l1 *= sc1;
            #pragma unroll
            for (int nt = 0; nt < 8; nt++) {
                oacc[nt][0] *= sc0; oacc[nt][1] *= sc0;
                oacc[nt][2] *= sc1; oacc[nt][3] *= sc1;
            }

            uint32_t* pw = pt + (w * 16 + lm) * ASTW;
            #pragma unroll
            for (int nt = 0; nt < 8; nt++) {
                const float p0 = __expf(sacc[nt][0] - m0);
                const float p1 = __expf(sacc[nt][1] - m0);
                const float p2 = __expf(sacc[nt][2] - m1);
                const float p3 = __expf(sacc[nt][3] - m1);
                l0 += p0 + p1;
                l1 += p2 + p3;
                pw[nt * 4 + lk]            = pack2(p0, p1);
                pw[8 * ASTW + nt * 4 + lk] = pack2(p2, p3);
            }
            __syncwarp();

            const uint32_t* pa = pt + (w * 16 + lm) * ASTW + lk;
            #pragma unroll
            for (int ks = 0; ks < 4; ks++) {
                const uint32_t a0 = pa[ks * 8];
                const uint32_t a1 = pa[8 * ASTW + ks * 8];
                const uint32_t a2 = pa[ks * 8 + 4];
                const uint32_t a3 = pa[8 * ASTW + ks * 8 + 4];
                #pragma unroll
                for (int nt = 0; nt < 8; nt++) {
                    const uint32_t* vb = vt + (nt * 8 + lm) * ASTW + ks * 8 + lk;
                    mma_f16(oacc[nt], a0, a1, a2, a3, vb[0], vb[4]);
                }
            }
        }
        __syncthreads();
    }

    // ---- finalize: write fp16 to g_ah ----
    l0 += __shfl_xor_sync(0xffffffffu, l0, 1);
    l0 += __shfl_xor_sync(0xffffffffu, l0, 2);
    l1 += __shfl_xor_sync(0xffffffffu, l1, 1);
    l1 += __shfl_xor_sync(0xffffffffu, l1, 2);
    const float inv0 = 1.f / l0;
    const float inv1 = 1.f / l1;

    uint32_t* og = (uint32_t*)g_ah +
        ((size_t)(b * SEQ + q0 + w * 16 + lm) * DMODEL + h * HDIM) / 2;
    #pragma unroll
    for (int nt = 0; nt < 8; nt++) {
        og[(nt * 8 + ln) / 2] = pack2(oacc[nt][0] * inv0, oacc[nt][1] * inv0);
        og[(8 * DMODEL + nt * 8 + ln) / 2] = pack2(oacc[nt][2] * inv1, oacc[nt][3] * inv1);
    }
}

// ---------------------------------------------------------------------------
// Launch
// ---------------------------------------------------------------------------
extern "C" void kernel_launch(void* const* d_in, const int* in_sizes, int n_in,
                              void* d_out, int out_size)
{
    (void)in_sizes; (void)n_in; (void)out_size;
    const float* x       = (const float*)d_in[0];
    const float* pos_cos = (const float*)d_in[1];
    const float* pos_sin = (const float*)d_in[2];
    const float* wq_w    = (const float*)d_in[3];
    const float* wq_b    = (const float*)d_in[4];
    const float* wk_w    = (const float*)d_in[5];
    const float* wk_b    = (const float*)d_in[6];
    const float* wv_w    = (const float*)d_in[7];
    const float* wv_b    = (const float*)d_in[8];
    const float* wo_w    = (const float*)d_in[9];
    const float* wo_b    = (const float*)d_in[10];
    float* out = (float*)d_out;

    __half *xh, *whq, *whk, *whv, *who, *qh, *kh, *vh, *ah;
    cudaGetSymbolAddress((void**)&xh,  g_xh);
    cudaGetSymbolAddress((void**)&whq, g_whq);
    cudaGetSymbolAddress((void**)&whk, g_whk);
    cudaGetSymbolAddress((void**)&whv, g_whv);
    cudaGetSymbolAddress((void**)&who, g_who);
    cudaGetSymbolAddress((void**)&qh,  g_qh);
    cudaGetSymbolAddress((void**)&kh,  g_kh);
    cudaGetSymbolAddress((void**)&vh,  g_vh);
    cudaGetSymbolAddress((void**)&ah,  g_ah);

    cudaFuncSetAttribute(gemm_f16_kernel,
                         cudaFuncAttributeMaxDynamicSharedMemorySize, SMEM_DYN);
    cudaFuncSetAttribute(attn_mma_kernel,
                         cudaFuncAttributeMaxDynamicSharedMemorySize, ATTN_SMEM);

    // fp32 -> fp16 conversions (Q weight+bias pre-scaled by 1/sqrt(hd))
    const int X4 = MROWS * DMODEL / 4;
    const int W4 = DMODEL * DMODEL / 4;
    cvt_f2h_kernel<<<1024, 256>>>((const float4*)x,    (uint2*)xh,  X4, 1.0f);
    cvt_f2h_kernel<<<512,  256>>>((const float4*)wq_w, (uint2*)whq, W4, 0.125f);
    cvt_f2h_kernel<<<512,  256>>>((const float4*)wk_w, (uint2*)whk, W4, 1.0f);
    cvt_f2h_kernel<<<512,  256>>>((const float4*)wv_w, (uint2*)whv, W4, 1.0f);
    cvt_f2h_kernel<<<512,  256>>>((const float4*)wo_w, (uint2*)who, W4, 1.0f);

    dim3 gg(DMODEL / BN, MROWS / BM);   // (8, 32)
    gemm_f16_kernel<<<gg, 256, SMEM_DYN>>>(xh, whq, wq_b, 0.125f, qh, 1,
                                           pos_cos, pos_sin, 1);
    gemm_f16_kernel<<<gg, 256, SMEM_DYN>>>(xh, whk, wk_b, 1.0f,  kh, 1,
                                           pos_cos, pos_sin, 1);
    gemm_f16_kernel<<<gg, 256, SMEM_DYN>>>(xh, whv, wv_b, 1.0f,  vh, 1,
                                           pos_cos, pos_sin, 0);

    dim3 ga(SEQ / 128, NHEAD, BATCH);   // (16, 16, 2)
    attn_mma_kernel<<<ga, 256, ATTN_SMEM>>>();

    gemm_f16_kernel<<<gg, 256, SMEM_DYN>>>(ah, who, wo_b, 1.0f, out, 0,
                                           pos_cos, pos_sin, 0);
}

// round 13
// speedup vs baseline: 3.1167x; 1.1557x over previous
#include <cuda_runtime.h>
#include <cuda_fp16.h>
#include <cstdint>
#include <math.h>

// Problem constants
#define BATCH 2
#define SEQ   2048
#define DMODEL 1024
#define NHEAD 16
#define HDIM  64
#define HALF  32
#define MROWS (BATCH * SEQ)   // 4096

// Scratch (static device globals — allocation-free rule)
__device__ __half g_xh[MROWS * DMODEL];
__device__ __half g_whq[DMODEL * DMODEL];
__device__ __half g_whk[DMODEL * DMODEL];
__device__ __half g_whv[DMODEL * DMODEL];
__device__ __half g_who[DMODEL * DMODEL];
__device__ __half g_qh[MROWS * DMODEL];
__device__ __half g_kh[MROWS * DMODEL];
__device__ __half g_vh[MROWS * DMODEL];
__device__ __half g_ah[MROWS * DMODEL];

__device__ __forceinline__ uint32_t pack2(float a, float b) {
    __half2 h = __floats2half2_rn(a, b);
    return *reinterpret_cast<uint32_t*>(&h);
}

__device__ __forceinline__ void mma_f16(float c[4], uint32_t a0, uint32_t a1,
                                        uint32_t a2, uint32_t a3,
                                        uint32_t b0, uint32_t b1) {
    asm volatile(
        "mma.sync.aligned.m16n8k16.row.col.f32.f16.f16.f32 "
        "{%0,%1,%2,%3}, {%4,%5,%6,%7}, {%8,%9}, {%0,%1,%2,%3};"
        : "+f"(c[0]), "+f"(c[1]), "+f"(c[2]), "+f"(c[3])
        : "r"(a0), "r"(a1), "r"(a2), "r"(a3), "r"(b0), "r"(b1));
}

__device__ __forceinline__ void ldmx4(uint32_t& r0, uint32_t& r1,
                                      uint32_t& r2, uint32_t& r3, uint32_t addr) {
    asm volatile("ldmatrix.sync.aligned.m8n8.x4.shared.b16 {%0,%1,%2,%3}, [%4];"
                 : "=r"(r0), "=r"(r1), "=r"(r2), "=r"(r3) : "r"(addr));
}

__device__ __forceinline__ uint32_t smem_u32(const void* p) {
    uint32_t a;
    asm("{ .reg .u64 t; cvta.to.shared.u64 t, %1; cvt.u32.u64 %0, t; }"
        : "=r"(a) : "l"(p));
    return a;
}

__device__ __forceinline__ void cp16(uint32_t dst, const void* src) {
    asm volatile("cp.async.cg.shared.global [%0], [%1], 16;"
                 :: "r"(dst), "l"(src));
}
#define CP_COMMIT() asm volatile("cp.async.commit_group;" ::: "memory")
#define CP_WAIT1()  asm volatile("cp.async.wait_group 1;"  ::: "memory")

// ---------------------------------------------------------------------------
// fp32 -> fp16 conversions
// ---------------------------------------------------------------------------
__global__ void cvt_f2h_kernel(const float4* __restrict__ in,
                               uint2* __restrict__ out, int n4, float scale)
{
    for (int i = blockIdx.x * blockDim.x + threadIdx.x; i < n4;
         i += gridDim.x * blockDim.x) {
        float4 v = in[i];
        uint2 o;
        o.x = pack2(v.x * scale, v.y * scale);
        o.y = pack2(v.z * scale, v.w * scale);
        out[i] = o;
    }
}

// all 4 weight matrices in one launch (blockIdx.y selects matrix)
__global__ void cvt_w_kernel(const float4* __restrict__ w0, const float4* __restrict__ w1,
                             const float4* __restrict__ w2, const float4* __restrict__ w3,
                             uint2* __restrict__ o0, uint2* __restrict__ o1,
                             uint2* __restrict__ o2, uint2* __restrict__ o3, int n4)
{
    const int which = blockIdx.y;
    const float4* in = which == 0 ? w0 : which == 1 ? w1 : which == 2 ? w2 : w3;
    uint2* out       = which == 0 ? o0 : which == 1 ? o1 : which == 2 ? o2 : o3;
    const float scale = which == 0 ? 0.125f : 1.0f;
    for (int i = blockIdx.x * blockDim.x + threadIdx.x; i < n4;
         i += gridDim.x * blockDim.x) {
        float4 v = in[i];
        uint2 o;
        o.x = pack2(v.x * scale, v.y * scale);
        o.y = pack2(v.z * scale, v.w * scale);
        out[i] = o;
    }
}

// ---------------------------------------------------------------------------
// fp16 GEMM, cp.async 3-stage pipeline + ldmatrix fragment loads.
// C = A @ W^T + bias*bscale (+RoPE). CTA 128x128, 8 warps, 64x32 warp tiles.
// ---------------------------------------------------------------------------
#define BM 128
#define BN 128
#define KC 32
#define NT (DMODEL / KC)       // 32
#define GST 20                 // words per smem row
#define GTILEW (128 * GST)
#define NSTAGE 3
#define SMEM_DYN (NSTAGE * 2 * GTILEW * 4)   // 61440 bytes

__global__ void __launch_bounds__(256, 2)
gemm_f16_kernel(const __half* __restrict__ A,
                const __half* __restrict__ W,
                const float* __restrict__ bias,
                float bscale,
                void* __restrict__ Cout,
                int outHalf,
                const float* __restrict__ cosb,
                const float* __restrict__ sinb,
                int applyRope)
{
    extern __shared__ uint32_t su[];
    const uint32_t sbase = smem_u32(su);

    const int tid = threadIdx.x;
    const int wid = tid >> 5;
    const int lid = tid & 31;
    const int wm = (wid & 1) * 64;
    const int wn = (wid >> 1) * 32;
    const int m0 = blockIdx.y * BM;
    const int n0 = blockIdx.x * BN;

    const __half* Abase = A + (size_t)m0 * DMODEL;
    const __half* Wbase = W + (size_t)n0 * DMODEL;

    // cp.async staging: 512 x 16B segs per operand (4 segs/row); 2/thread
    const int r0_ = tid >> 2;
    const int r1_ = (tid + 256) >> 2;
    const int sg_ = (tid & 3) * 4;

    #define CPLOAD(kt, stg) do {                                               \
        const __half* _as = Abase + (kt) * KC;                                 \
        const __half* _ws = Wbase + (kt) * KC;                                 \
        const uint32_t _ab = sbase + (2 * (stg)) * GTILEW * 4;                 \
        const uint32_t _bb = _ab + GTILEW * 4;                                 \
        cp16(_ab + (r0_ * GST + sg_) * 4, _as + (size_t)r0_ * DMODEL + sg_ * 2); \
        cp16(_ab + (r1_ * GST + sg_) * 4, _as + (size_t)r1_ * DMODEL + sg_ * 2); \
        cp16(_bb + (r0_ * GST + sg_) * 4, _ws + (size_t)r0_ * DMODEL + sg_ * 2); \
        cp16(_bb + (r1_ * GST + sg_) * 4, _ws + (size_t)r1_ * DMODEL + sg_ * 2); \
    } while (0)

    float acc[4][4][4];
    #pragma unroll
    for (int i = 0; i < 4; i++)
        #pragma unroll
        for (int j = 0; j < 4; j++)
            #pragma unroll
            for (int r = 0; r < 4; r++) acc[i][j][r] = 0.f;

    // ldmatrix per-thread byte offsets (stage-invariant)
    uint32_t aoff[4], boff[2];
    #pragma unroll
    for (int mf = 0; mf < 4; mf++)
        aoff[mf] = ((wm + mf * 16 + (lid & 15)) * GST + (lid >> 4) * 4) * 4;
    #pragma unroll
    for (int p = 0; p < 2; p++)
        boff[p] = ((wn + p * 16 + (lid & 7) + ((lid >> 4) & 1) * 8) * GST
                   + ((lid >> 3) & 1) * 4) * 4;

    CPLOAD(0, 0); CP_COMMIT();
    CPLOAD(1, 1); CP_COMMIT();

    for (int kt = 0; kt < NT; kt++) {
        CP_WAIT1();
        __syncthreads();
        if (kt + 2 < NT) CPLOAD(kt + 2, (kt + 2) % NSTAGE);
        CP_COMMIT();

        const uint32_t aB = sbase + (2 * (kt % NSTAGE)) * GTILEW * 4;
        const uint32_t bB = aB + GTILEW * 4;
        #pragma unroll
        for (int ks = 0; ks < 2; ks++) {
            uint32_t af[4][4];
            #pragma unroll
            for (int mf = 0; mf < 4; mf++)
                ldmx4(af[mf][0], af[mf][1], af[mf][2], af[mf][3],
                      aB + aoff[mf] + ks * 32);
            #pragma unroll
            for (int p = 0; p < 2; p++) {
                uint32_t b00, b01, b10, b11;
                ldmx4(b00, b01, b10, b11, bB + boff[p] + ks * 32);
                #pragma unroll
                for (int mf = 0; mf < 4; mf++) {
                    mma_f16(acc[mf][2 * p    ], af[mf][0], af[mf][1], af[mf][2], af[mf][3], b00, b01);
                    mma_f16(acc[mf][2 * p + 1], af[mf][0], af[mf][1], af[mf][2], af[mf][3], b10, b11);
                }
            }
        }
    }

    // epilogue: bias*bscale (+ RoPE), store fp16 or fp32
    const int lm = lid >> 2;
    const int ln = (lid & 3) * 2;
    #pragma unroll
    for (int mf = 0; mf < 4; mf++) {
        #pragma unroll
        for (int half_ = 0; half_ < 2; half_++) {
            const int m = m0 + wm + mf * 16 + lm + half_ * 8;
            const int spos = m & (SEQ - 1);
            #pragma unroll
            for (int nf = 0; nf < 4; nf++) {
                const int n = n0 + wn + nf * 8 + ln;
                float v0 = acc[mf][nf][half_ * 2 + 0] + bias[n] * bscale;
                float v1 = acc[mf][nf][half_ * 2 + 1] + bias[n + 1] * bscale;
                if (applyRope) {
                    const int fi = (n & (HDIM - 1)) >> 1;
                    const float cc = cosb[spos * HALF + fi];
                    const float ss = sinb[spos * HALF + fi];
                    const float t0 = v0 * cc - v1 * ss;
                    const float t1 = v0 * ss + v1 * cc;
                    v0 = t0; v1 = t1;
                }
                if (outHalf) {
                    uint32_t* crow = (uint32_t*)Cout + (size_t)m * (DMODEL / 2);
                    crow[n / 2] = pack2(v0, v1);
                } else {
                    float* crow = (float*)Cout + (size_t)m * DMODEL;
                    float2 st; st.x = v0; st.y = v1;
                    *(float2*)(crow + n) = st;
                }
            }
        }
    }
}

// ---------------------------------------------------------------------------
// fp16 flash attention with ldmatrix fragment loads. 2 CTAs/SM.
// CTA = 128 queries of one (b,h); 8 warps x 16 rows; KV tiles of 64.
// ---------------------------------------------------------------------------
#define ASTW 36
#define KTW (64 * ASTW)
#define VTW (64 * ASTW)
#define PTW (128 * ASTW)
#define ATTN_SMEM ((KTW + VTW + PTW) * 4)   // 36864 bytes

__global__ void __launch_bounds__(256, 2)
attn_mma_kernel()
{
    extern __shared__ uint32_t su[];
    uint32_t* kt = su;
    uint32_t* vt = kt + KTW;
    uint32_t* pt = vt + VTW;
    const uint32_t ktB = smem_u32(kt);
    const uint32_t vtB = smem_u32(vt);
    const uint32_t ptB = smem_u32(pt);

    const int b  = blockIdx.z;
    const int h  = blockIdx.y;
    const int q0 = ((int)gridDim.x - 1 - (int)blockIdx.x) * 128;  // heavy first
    const int tid = threadIdx.x;
    const int w   = tid >> 5;
    const int lid = tid & 31;
    const int lm = lid >> 2;
    const int lk = lid & 3;
    const int ln = lk * 2;

    // ldmatrix offsets
    const uint32_t poff =
        ((w * 16 + (lid & 15)) * ASTW + (lid >> 4) * 4) * 4;           // A-frag (Q/P)
    uint32_t bo[4];
    #pragma unroll
    for (int g = 0; g < 4; g++)
        bo[g] = ((g * 16 + (lid & 7) + ((lid >> 4) & 1) * 8) * ASTW
                 + ((lid >> 3) & 1) * 4) * 4;                           // B-frag (K/V)

    // ---- stage Q into pt: 128 rows x 8 segs ----
    const __half* qg = g_qh + ((size_t)(b * SEQ + q0) * DMODEL + h * HDIM);
    #pragma unroll
    for (int i = 0; i < 4; i++) {
        int s = tid + i * 256;
        int row = s >> 3;
        int sg  = (s & 7) * 4;
        uint4 v = *(const uint4*)(qg + (size_t)row * DMODEL + sg * 2);
        *(uint4*)(pt + row * ASTW + sg) = v;
    }
    __syncthreads();

    uint32_t aq[4][4];
    #pragma unroll
    for (int ks = 0; ks < 4; ks++)
        ldmx4(aq[ks][0], aq[ks][1], aq[ks][2], aq[ks][3], ptB + poff + ks * 32);

    float m0 = -1e30f, m1 = -1e30f, l0 = 0.f, l1 = 0.f;
    float oacc[8][4];
    #pragma unroll
    for (int nt = 0; nt < 8; nt++)
        #pragma unroll
        for (int r = 0; r < 4; r++) oacc[nt][r] = 0.f;

    const __half* kg = g_kh + ((size_t)(b * SEQ) * DMODEL + h * HDIM);
    const __half* vg = g_vh + ((size_t)(b * SEQ) * DMODEL + h * HDIM);

    const int ntiles = q0 / 64 + 2;
    for (int t = 0; t < ntiles; t++) {
        const int kv0 = t * 64;
        // K tile: 64 rows x 8 segs
        #pragma unroll
        for (int i = 0; i < 2; i++) {
            int s = tid + i * 256;
            int row = s >> 3;
            int sg  = (s & 7) * 4;
            uint4 v = *(const uint4*)(kg + (size_t)(kv0 + row) * DMODEL + sg * 2);
            *(uint4*)(kt + row * ASTW + sg) = v;
        }
        // V tile transposed: vt[d][kvpair]
        #pragma unroll
        for (int i = 0; i < 2; i++) {
            int task = tid + i * 256;
            int kvp = task & 31;
            int d0  = (task >> 5) * 4;
            const __half* e = vg + (size_t)(kv0 + 2 * kvp) * DMODEL + d0;
            uint2 we = *(const uint2*)e;
            uint2 wo = *(const uint2*)(e + DMODEL);
            vt[(d0 + 0) * ASTW + kvp] = __byte_perm(we.x, wo.x, 0x5410);
            vt[(d0 + 1) * ASTW + kvp] = __byte_perm(we.x, wo.x, 0x7632);
            vt[(d0 + 2) * ASTW + kvp] = __byte_perm(we.y, wo.y, 0x5410);
            vt[(d0 + 3) * ASTW + kvp] = __byte_perm(we.y, wo.y, 0x7632);
        }
        __syncthreads();

        const bool active = !(w < 4 && t == ntiles - 1);   // warp-uniform
        if (active) {
            // ---- S = Q K^T ----
            float sacc[8][4];
            #pragma unroll
            for (int nt = 0; nt < 8; nt++)
                #pragma unroll
                for (int r = 0; r < 4; r++) sacc[nt][r] = 0.f;

            #pragma unroll
            for (int ks = 0; ks < 4; ks++) {
                #pragma unroll
                for (int g = 0; g < 4; g++) {
                    uint32_t b00, b01, b10, b11;
                    ldmx4(b00, b01, b10, b11, ktB + bo[g] + ks * 32);
                    mma_f16(sacc[2 * g    ], aq[ks][0], aq[ks][1], aq[ks][2], aq[ks][3], b00, b01);
                    mma_f16(sacc[2 * g + 1], aq[ks][0], aq[ks][1], aq[ks][2], aq[ks][3], b10, b11);
                }
            }

            if (t >= ntiles - 2) {
                const int rel0 = q0 + w * 16 + lm - kv0;
                const int rel1 = rel0 + 8;
                #pragma unroll
                for (int nt = 0; nt < 8; nt++) {
                    const int c0 = nt * 8 + ln;
                    if (c0     > rel0) sacc[nt][0] = -1e30f;
                    if (c0 + 1 > rel0) sacc[nt][1] = -1e30f;
                    if (c0     > rel1) sacc[nt][2] = -1e30f;
                    if (c0 + 1 > rel1) sacc[nt][3] = -1e30f;
                }
            }

            float rm0 = -1e30f, rm1 = -1e30f;
            #pragma unroll
            for (int nt = 0; nt < 8; nt++) {
                rm0 = fmaxf(rm0, fmaxf(sacc[nt][0], sacc[nt][1]));
                rm1 = fmaxf(rm1, fmaxf(sacc[nt][2], sacc[nt][3]));
            }
            rm0 = fmaxf(rm0, __shfl_xor_sync(0xffffffffu, rm0, 1));
            rm0 = fmaxf(rm0, __shfl_xor_sync(0xffffffffu, rm0, 2));
            rm1 = fmaxf(rm1, __shfl_xor_sync(0xffffffffu, rm1, 1));
            rm1 = fmaxf(rm1, __shfl_xor_sync(0xffffffffu, rm1, 2));

            const float mn0 = fmaxf(m0, rm0);
            const float mn1 = fmaxf(m1, rm1);
            const float sc0 = __expf(m0 - mn0);
            const float sc1 = __expf(m1 - mn1);
            m0 = mn0; m1 = mn1;
            l0 *= sc0; l1 *= sc1;
            #pragma unroll
            for (int nt = 0; nt < 8; nt++) {
                oacc[nt][0] *= sc0; oacc[nt][1] *= sc0;
                oacc[nt][2] *= sc1; oacc[nt][3] *= sc1;
            }

            uint32_t* pw = pt + (w * 16 + lm) * ASTW;
            #pragma unroll
            for (int nt = 0; nt < 8; nt++) {
                const float p0 = __expf(sacc[nt][0] - m0);
                const float p1 = __expf(sacc[nt][1] - m0);
                const float p2 = __expf(sacc[nt][2] - m1);
                const float p3 = __expf(sacc[nt][3] - m1);
                l0 += p0 + p1;
                l1 += p2 + p3;
                pw[nt * 4 + lk]            = pack2(p0, p1);
                pw[8 * ASTW + nt * 4 + lk] = pack2(p2, p3);
            }
            __syncwarp();

            // ---- O += P V ----
            #pragma unroll
            for (int ks = 0; ks < 4; ks++) {
                uint32_t a0, a1, a2, a3;
                ldmx4(a0, a1, a2, a3, ptB + poff + ks * 32);
                #pragma unroll
                for (int g = 0; g < 4; g++) {
                    uint32_t b00, b01, b10, b11;
                    ldmx4(b00, b01, b10, b11, vtB + bo[g] + ks * 32);
                    mma_f16(oacc[2 * g    ], a0, a1, a2, a3, b00, b01);
                    mma_f16(oacc[2 * g + 1], a0, a1, a2, a3, b10, b11);
                }
            }
        }
        __syncthreads();
    }

    // ---- finalize: write fp16 to g_ah ----
    l0 += __shfl_xor_sync(0xffffffffu, l0, 1);
    l0 += __shfl_xor_sync(0xffffffffu, l0, 2);
    l1 += __shfl_xor_sync(0xffffffffu, l1, 1);
    l1 += __shfl_xor_sync(0xffffffffu, l1, 2);
    const float inv0 = 1.f / l0;
    const float inv1 = 1.f / l1;

    uint32_t* og = (uint32_t*)g_ah +
        ((size_t)(b * SEQ + q0 + w * 16 + lm) * DMODEL + h * HDIM) / 2;
    #pragma unroll
    for (int nt = 0; nt < 8; nt++) {
        og[(nt * 8 + ln) / 2] = pack2(oacc[nt][0] * inv0, oacc[nt][1] * inv0);
        og[(8 * DMODEL + nt * 8 + ln) / 2] = pack2(oacc[nt][2] * inv1, oacc[nt][3] * inv1);
    }
}

// ---------------------------------------------------------------------------
// Launch
// ---------------------------------------------------------------------------
extern "C" void kernel_launch(void* const* d_in, const int* in_sizes, int n_in,
                              void* d_out, int out_size)
{
    (void)in_sizes; (void)n_in; (void)out_size;
    const float* x       = (const float*)d_in[0];
    const float* pos_cos = (const float*)d_in[1];
    const float* pos_sin = (const float*)d_in[2];
    const float* wq_w    = (const float*)d_in[3];
    const float* wq_b    = (const float*)d_in[4];
    const float* wk_w    = (const float*)d_in[5];
    const float* wk_b    = (const float*)d_in[6];
    const float* wv_w    = (const float*)d_in[7];
    const float* wv_b    = (const float*)d_in[8];
    const float* wo_w    = (const float*)d_in[9];
    const float* wo_b    = (const float*)d_in[10];
    float* out = (float*)d_out;

    __half *xh, *whq, *whk, *whv, *who, *qh, *kh, *vh, *ah;
    cudaGetSymbolAddress((void**)&xh,  g_xh);
    cudaGetSymbolAddress((void**)&whq, g_whq);
    cudaGetSymbolAddress((void**)&whk, g_whk);
    cudaGetSymbolAddress((void**)&whv, g_whv);
    cudaGetSymbolAddress((void**)&who, g_who);
    cudaGetSymbolAddress((void**)&qh,  g_qh);
    cudaGetSymbolAddress((void**)&kh,  g_kh);
    cudaGetSymbolAddress((void**)&vh,  g_vh);
    cudaGetSymbolAddress((void**)&ah,  g_ah);

    cudaFuncSetAttribute(gemm_f16_kernel,
                         cudaFuncAttributeMaxDynamicSharedMemorySize, SMEM_DYN);
    cudaFuncSetAttribute(attn_mma_kernel,
                         cudaFuncAttributeMaxDynamicSharedMemorySize, ATTN_SMEM);

    // fp32 -> fp16 conversions (Q weight pre-scaled by 1/sqrt(hd))
    const int X4 = MROWS * DMODEL / 4;
    const int W4 = DMODEL * DMODEL / 4;
    cvt_f2h_kernel<<<1024, 256>>>((const float4*)x, (uint2*)xh, X4, 1.0f);
    dim3 gw(128, 4);
    cvt_w_kernel<<<gw, 256>>>((const float4*)wq_w, (const float4*)wk_w,
                              (const float4*)wv_w, (const float4*)wo_w,
                              (uint2*)whq, (uint2*)whk, (uint2*)whv, (uint2*)who, W4);

    dim3 gg(DMODEL / BN, MROWS / BM);   // (8, 32)
    gemm_f16_kernel<<<gg, 256, SMEM_DYN>>>(xh, whq, wq_b, 0.125f, qh, 1,
                                           pos_cos, pos_sin, 1);
    gemm_f16_kernel<<<gg, 256, SMEM_DYN>>>(xh, whk, wk_b, 1.0f,  kh, 1,
                                           pos_cos, pos_sin, 1);
    gemm_f16_kernel<<<gg, 256, SMEM_DYN>>>(xh, whv, wv_b, 1.0f,  vh, 1,
                                           pos_cos, pos_sin, 0);

    dim3 ga(SEQ / 128, NHEAD, BATCH);   // (16, 16, 2)
    attn_mma_kernel<<<ga, 256, ATTN_SMEM>>>();

    gemm_f16_kernel<<<gg, 256, SMEM_DYN>>>(ah, who, wo_b, 1.0f, out, 0,
                                           pos_cos, pos_sin, 0);
}

// round 14
// speedup vs baseline: 3.2981x; 1.0582x over previous
#include <cuda_runtime.h>
#include <cuda_fp16.h>
#include <cstdint>
#include <math.h>

// Problem constants
#define BATCH 2
#define SEQ   2048
#define DMODEL 1024
#define NHEAD 16
#define HDIM  64
#define HALF  32
#define MROWS (BATCH * SEQ)   // 4096

// Scratch (static device globals — allocation-free rule)
__device__ __half g_xh[MROWS * DMODEL];
__device__ __half g_whq[DMODEL * DMODEL];
__device__ __half g_whk[DMODEL * DMODEL];
__device__ __half g_whv[DMODEL * DMODEL];
__device__ __half g_who[DMODEL * DMODEL];
__device__ __half g_qh[MROWS * DMODEL];
__device__ __half g_kh[MROWS * DMODEL];
__device__ __half g_vh[MROWS * DMODEL];
__device__ __half g_ah[MROWS * DMODEL];

__device__ __forceinline__ uint32_t pack2(float a, float b) {
    __half2 h = __floats2half2_rn(a, b);
    return *reinterpret_cast<uint32_t*>(&h);
}

__device__ __forceinline__ void mma_f16(float c[4], uint32_t a0, uint32_t a1,
                                        uint32_t a2, uint32_t a3,
                                        uint32_t b0, uint32_t b1) {
    asm volatile(
        "mma.sync.aligned.m16n8k16.row.col.f32.f16.f16.f32 "
        "{%0,%1,%2,%3}, {%4,%5,%6,%7}, {%8,%9}, {%0,%1,%2,%3};"
        : "+f"(c[0]), "+f"(c[1]), "+f"(c[2]), "+f"(c[3])
        : "r"(a0), "r"(a1), "r"(a2), "r"(a3), "r"(b0), "r"(b1));
}

__device__ __forceinline__ void ldmx4(uint32_t& r0, uint32_t& r1,
                                      uint32_t& r2, uint32_t& r3, uint32_t addr) {
    asm volatile("ldmatrix.sync.aligned.m8n8.x4.shared.b16 {%0,%1,%2,%3}, [%4];"
                 : "=r"(r0), "=r"(r1), "=r"(r2), "=r"(r3) : "r"(addr));
}

__device__ __forceinline__ uint32_t smem_u32(const void* p) {
    uint32_t a;
    asm("{ .reg .u64 t; cvta.to.shared.u64 t, %1; cvt.u32.u64 %0, t; }"
        : "=r"(a) : "l"(p));
    return a;
}

__device__ __forceinline__ void cp16(uint32_t dst, const void* src) {
    asm volatile("cp.async.cg.shared.global [%0], [%1], 16;"
                 :: "r"(dst), "l"(src));
}
#define CP_COMMIT() asm volatile("cp.async.commit_group;" ::: "memory")
#define CP_WAIT1()  asm volatile("cp.async.wait_group 1;"  ::: "memory")

// ---------------------------------------------------------------------------
// fp32 -> fp16 conversions
// ---------------------------------------------------------------------------
__global__ void cvt_f2h_kernel(const float4* __restrict__ in,
                               uint2* __restrict__ out, int n4, float scale)
{
    for (int i = blockIdx.x * blockDim.x + threadIdx.x; i < n4;
         i += gridDim.x * blockDim.x) {
        float4 v = in[i];
        uint2 o;
        o.x = pack2(v.x * scale, v.y * scale);
        o.y = pack2(v.z * scale, v.w * scale);
        out[i] = o;
    }
}

__global__ void cvt_w_kernel(const float4* __restrict__ w0, const float4* __restrict__ w1,
                             const float4* __restrict__ w2, const float4* __restrict__ w3,
                             uint2* __restrict__ o0, uint2* __restrict__ o1,
                             uint2* __restrict__ o2, uint2* __restrict__ o3, int n4)
{
    const int which = blockIdx.y;
    const float4* in = which == 0 ? w0 : which == 1 ? w1 : which == 2 ? w2 : w3;
    uint2* out       = which == 0 ? o0 : which == 1 ? o1 : which == 2 ? o2 : o3;
    const float scale = which == 0 ? 0.125f : 1.0f;
    for (int i = blockIdx.x * blockDim.x + threadIdx.x; i < n4;
         i += gridDim.x * blockDim.x) {
        float4 v = in[i];
        uint2 o;
        o.x = pack2(v.x * scale, v.y * scale);
        o.y = pack2(v.z * scale, v.w * scale);
        out[i] = o;
    }
}

// ---------------------------------------------------------------------------
// fp16 GEMM, cp.async 3-stage pipeline + ldmatrix, KC=64 (16 chunks).
// blockIdx.z selects among up to 3 (W, bias, out) sets (fused QKV).
// ---------------------------------------------------------------------------
#define BM 128
#define BN 128
#define KC 64
#define NT (DMODEL / KC)       // 16
#define GST 36                 // words per smem row (32 data + 4 pad)
#define GTILEW (128 * GST)     // 4608 words = 18432 B
#define NSTAGE 3
#define SMEM_DYN (NSTAGE * 2 * GTILEW * 4)   // 110592 bytes

__global__ void __launch_bounds__(256, 2)
gemm_f16_kernel(const __half* __restrict__ A,
                const __half* __restrict__ W0, const __half* __restrict__ W1,
                const __half* __restrict__ W2,
                const float* __restrict__ b0, const float* __restrict__ b1,
                const float* __restrict__ b2,
                void* __restrict__ o0, void* __restrict__ o1, void* __restrict__ o2,
                float bscale0,
                int outHalf,
                const float* __restrict__ cosb,
                const float* __restrict__ sinb,
                int ropeMask)
{
    extern __shared__ uint32_t su[];
    const uint32_t sbase = smem_u32(su);

    const int z = blockIdx.z;
    const __half* W  = z == 0 ? W0 : z == 1 ? W1 : W2;
    const float* bias = z == 0 ? b0 : z == 1 ? b1 : b2;
    void* Cout = z == 0 ? o0 : z == 1 ? o1 : o2;
    const float bscale = z == 0 ? bscale0 : 1.0f;
    const int applyRope = (ropeMask >> z) & 1;

    const int tid = threadIdx.x;
    const int wid = tid >> 5;
    const int lid = tid & 31;
    const int wm = (wid & 1) * 64;
    const int wn = (wid >> 1) * 32;
    const int m0 = blockIdx.y * BM;
    const int n0 = blockIdx.x * BN;

    const __half* Abase = A + (size_t)m0 * DMODEL;
    const __half* Wbase = W + (size_t)n0 * DMODEL;

    // cp.async staging: 1024 x 16B segs per operand (8/row); 4/thread/operand
    #define CPLOAD(kt, stg) do {                                               \
        const __half* _as = Abase + (kt) * KC;                                 \
        const __half* _ws = Wbase + (kt) * KC;                                 \
        const uint32_t _ab = sbase + (2 * (stg)) * GTILEW * 4;                 \
        const uint32_t _bb = _ab + GTILEW * 4;                                 \
        _Pragma("unroll")                                                      \
        for (int _i = 0; _i < 4; _i++) {                                       \
            int _s = tid + _i * 256;                                           \
            int _r = _s >> 3, _sg = (_s & 7) * 4;                              \
            cp16(_ab + (_r * GST + _sg) * 4, _as + (size_t)_r * DMODEL + _sg * 2); \
            cp16(_bb + (_r * GST + _sg) * 4, _ws + (size_t)_r * DMODEL + _sg * 2); \
        }                                                                      \
    } while (0)

    float acc[4][4][4];
    #pragma unroll
    for (int i = 0; i < 4; i++)
        #pragma unroll
        for (int j = 0; j < 4; j++)
            #pragma unroll
            for (int r = 0; r < 4; r++) acc[i][j][r] = 0.f;

    // ldmatrix per-thread byte offsets (stage-invariant)
    uint32_t aoff[4], boff[2];
    #pragma unroll
    for (int mf = 0; mf < 4; mf++)
        aoff[mf] = ((wm + mf * 16 + (lid & 15)) * GST + (lid >> 4) * 4) * 4;
    #pragma unroll
    for (int p = 0; p < 2; p++)
        boff[p] = ((wn + p * 16 + (lid & 7) + ((lid >> 4) & 1) * 8) * GST
                   + ((lid >> 3) & 1) * 4) * 4;

    CPLOAD(0, 0); CP_COMMIT();
    CPLOAD(1, 1); CP_COMMIT();

    for (int kt = 0; kt < NT; kt++) {
        CP_WAIT1();
        __syncthreads();
        if (kt + 2 < NT) CPLOAD(kt + 2, (kt + 2) % NSTAGE);
        CP_COMMIT();

        const uint32_t aB = sbase + (2 * (kt % NSTAGE)) * GTILEW * 4;
        const uint32_t bB = aB + GTILEW * 4;
        #pragma unroll
        for (int ks = 0; ks < 4; ks++) {       // KC/16
            uint32_t af[4][4];
            #pragma unroll
            for (int mf = 0; mf < 4; mf++)
                ldmx4(af[mf][0], af[mf][1], af[mf][2], af[mf][3],
                      aB + aoff[mf] + ks * 32);
            #pragma unroll
            for (int p = 0; p < 2; p++) {
                uint32_t b00, b01, b10, b11;
                ldmx4(b00, b01, b10, b11, bB + boff[p] + ks * 32);
                #pragma unroll
                for (int mf = 0; mf < 4; mf++) {
                    mma_f16(acc[mf][2 * p    ], af[mf][0], af[mf][1], af[mf][2], af[mf][3], b00, b01);
                    mma_f16(acc[mf][2 * p + 1], af[mf][0], af[mf][1], af[mf][2], af[mf][3], b10, b11);
                }
            }
        }
    }

    // epilogue: bias*bscale (+ RoPE), store fp16 or fp32
    const int lm = lid >> 2;
    const int ln = (lid & 3) * 2;
    #pragma unroll
    for (int mf = 0; mf < 4; mf++) {
        #pragma unroll
        for (int half_ = 0; half_ < 2; half_++) {
            const int m = m0 + wm + mf * 16 + lm + half_ * 8;
            const int spos = m & (SEQ - 1);
            #pragma unroll
            for (int nf = 0; nf < 4; nf++) {
                const int n = n0 + wn + nf * 8 + ln;
                float v0 = acc[mf][nf][half_ * 2 + 0] + bias[n] * bscale;
                float v1 = acc[mf][nf][half_ * 2 + 1] + bias[n + 1] * bscale;
                if (applyRope) {
                    const int fi = (n & (HDIM - 1)) >> 1;
                    const float cc = cosb[spos * HALF + fi];
                    const float ss = sinb[spos * HALF + fi];
                    const float t0 = v0 * cc - v1 * ss;
                    const float t1 = v0 * ss + v1 * cc;
                    v0 = t0; v1 = t1;
                }
                if (outHalf) {
                    uint32_t* crow = (uint32_t*)Cout + (size_t)m * (DMODEL / 2);
                    crow[n / 2] = pack2(v0, v1);
                } else {
                    float* crow = (float*)Cout + (size_t)m * DMODEL;
                    float2 st; st.x = v0; st.y = v1;
                    *(float2*)(crow + n) = st;
                }
            }
        }
    }
}

// ---------------------------------------------------------------------------
// fp16 flash attention with ldmatrix fragment loads. 2 CTAs/SM. (unchanged)
// ---------------------------------------------------------------------------
#define ASTW 36
#define KTW (64 * ASTW)
#define VTW (64 * ASTW)
#define PTW (128 * ASTW)
#define ATTN_SMEM ((KTW + VTW + PTW) * 4)   // 36864 bytes

__global__ void __launch_bounds__(256, 2)
attn_mma_kernel()
{
    extern __shared__ uint32_t su[];
    uint32_t* kt = su;
    uint32_t* vt = kt + KTW;
    uint32_t* pt = vt + VTW;
    const uint32_t ktB = smem_u32(kt);
    const uint32_t vtB = smem_u32(vt);
    const uint32_t ptB = smem_u32(pt);

    const int b  = blockIdx.z;
    const int h  = blockIdx.y;
    const int q0 = ((int)gridDim.x - 1 - (int)blockIdx.x) * 128;  // heavy first
    const int tid = threadIdx.x;
    const int w   = tid >> 5;
    const int lid = tid & 31;
    const int lm = lid >> 2;
    const int lk = lid & 3;
    const int ln = lk * 2;

    const uint32_t poff =
        ((w * 16 + (lid & 15)) * ASTW + (lid >> 4) * 4) * 4;
    uint32_t bo[4];
    #pragma unroll
    for (int g = 0; g < 4; g++)
        bo[g] = ((g * 16 + (lid & 7) + ((lid >> 4) & 1) * 8) * ASTW
                 + ((lid >> 3) & 1) * 4) * 4;

    const __half* qg = g_qh + ((size_t)(b * SEQ + q0) * DMODEL + h * HDIM);
    #pragma unroll
    for (int i = 0; i < 4; i++) {
        int s = tid + i * 256;
        int row = s >> 3;
        int sg  = (s & 7) * 4;
        uint4 v = *(const uint4*)(qg + (size_t)row * DMODEL + sg * 2);
        *(uint4*)(pt + row * ASTW + sg) = v;
    }
    __syncthreads();

    uint32_t aq[4][4];
    #pragma unroll
    for (int ks = 0; ks < 4; ks++)
        ldmx4(aq[ks][0], aq[ks][1], aq[ks][2], aq[ks][3], ptB + poff + ks * 32);

    float m0 = -1e30f, m1 = -1e30f, l0 = 0.f, l1 = 0.f;
    float oacc[8][4];
    #pragma unroll
    for (int nt = 0; nt < 8; nt++)
        #pragma unroll
        for (int r = 0; r < 4; r++) oacc[nt][r] = 0.f;

    const __half* kg = g_kh + ((size_t)(b * SEQ) * DMODEL + h * HDIM);
    const __half* vg = g_vh + ((size_t)(b * SEQ) * DMODEL + h * HDIM);

    const int ntiles = q0 / 64 + 2;
    for (int t = 0; t < ntiles; t++) {
        const int kv0 = t * 64;
        #pragma unroll
        for (int i = 0; i < 2; i++) {
            int s = tid + i * 256;
            int row = s >> 3;
            int sg  = (s & 7) * 4;
            uint4 v = *(const uint4*)(kg + (size_t)(kv0 + row) * DMODEL + sg * 2);
            *(uint4*)(kt + row * ASTW + sg) = v;
        }
        #pragma unroll
        for (int i = 0; i < 2; i++) {
            int task = tid + i * 256;
            int kvp = task & 31;
            int d0  = (task >> 5) * 4;
            const __half* e = vg + (size_t)(kv0 + 2 * kvp) * DMODEL + d0;
            uint2 we = *(const uint2*)e;
            uint2 wo = *(const uint2*)(e + DMODEL);
            vt[(d0 + 0) * ASTW + kvp] = __byte_perm(we.x, wo.x, 0x5410);
            vt[(d0 + 1) * ASTW + kvp] = __byte_perm(we.x, wo.x, 0x7632);
            vt[(d0 + 2) * ASTW + kvp] = __byte_perm(we.y, wo.y, 0x5410);
            vt[(d0 + 3) * ASTW + kvp] = __byte_perm(we.y, wo.y, 0x7632);
        }
        __syncthreads();

        const bool active = !(w < 4 && t == ntiles - 1);
        if (active) {
            float sacc[8][4];
            #pragma unroll
            for (int nt = 0; nt < 8; nt++)
                #pragma unroll
                for (int r = 0; r < 4; r++) sacc[nt][r] = 0.f;

            #pragma unroll
            for (int ks = 0; ks < 4; ks++) {
                #pragma unroll
                for (int g = 0; g < 4; g++) {
                    uint32_t b00, b01, b10, b11;
                    ldmx4(b00, b01, b10, b11, ktB + bo[g] + ks * 32);
                    mma_f16(sacc[2 * g    ], aq[ks][0], aq[ks][1], aq[ks][2], aq[ks][3], b00, b01);
                    mma_f16(sacc[2 * g + 1], aq[ks][0], aq[ks][1], aq[ks][2], aq[ks][3], b10, b11);
                }
            }

            if (t >= ntiles - 2) {
                const int rel0 = q0 + w * 16 + lm - kv0;
                const int rel1 = rel0 + 8;
                #pragma unroll
                for (int nt = 0; nt < 8; nt++) {
                    const int c0 = nt * 8 + ln;
                    if (c0     > rel0) sacc[nt][0] = -1e30f;
                    if (c0 + 1 > rel0) sacc[nt][1] = -1e30f;
                    if (c0     > rel1) sacc[nt][2] = -1e30f;
                    if (c0 + 1 > rel1) sacc[nt][3] = -1e30f;
                }
            }

            float rm0 = -1e30f, rm1 = -1e30f;
            #pragma unroll
            for (int nt = 0; nt < 8; nt++) {
                rm0 = fmaxf(rm0, fmaxf(sacc[nt][0], sacc[nt][1]));
                rm1 = fmaxf(rm1, fmaxf(sacc[nt][2], sacc[nt][3]));
            }
            rm0 = fmaxf(rm0, __shfl_xor_sync(0xffffffffu, rm0, 1));
            rm0 = fmaxf(rm0, __shfl_xor_sync(0xffffffffu, rm0, 2));
            rm1 = fmaxf(rm1, __shfl_xor_sync(0xffffffffu, rm1, 1));
            rm1 = fmaxf(rm1, __shfl_xor_sync(0xffffffffu, rm1, 2));

            const float mn0 = fmaxf(m0, rm0);
            const float mn1 = fmaxf(m1, rm1);
            const float sc0 = __expf(m0 - mn0);
            const float sc1 = __expf(m1 - mn1);
            m0 = mn0; m1 = mn1;
            l0 *= sc0; l1 *= sc1;
            #pragma unroll
            for (int nt = 0; nt < 8; nt++) {
                oacc[nt][0] *= sc0; oacc[nt][1] *= sc0;
                oacc[nt][2] *= sc1; oacc[nt][3] *= sc1;
            }

            uint32_t* pw = pt + (w * 16 + lm) * ASTW;
            #pragma unroll
            for (int nt = 0; nt < 8; nt++) {
                const float p0 = __expf(sacc[nt][0] - m0);
                const float p1 = __expf(sacc[nt][1] - m0);
                const float p2 = __expf(sacc[nt][2] - m1);
                const float p3 = __expf(sacc[nt][3] - m1);
                l0 += p0 + p1;
                l1 += p2 + p3;
                pw[nt * 4 + lk]            = pack2(p0, p1);
                pw[8 * ASTW + nt * 4 + lk] = pack2(p2, p3);
            }
            __syncwarp();

            #pragma unroll
            for (int ks = 0; ks < 4; ks++) {
                uint32_t a0, a1, a2, a3;
                ldmx4(a0, a1, a2, a3, ptB + poff + ks * 32);
                #pragma unroll
                for (int g = 0; g < 4; g++) {
                    uint32_t b00, b01, b10, b11;
                    ldmx4(b00, b01, b10, b11, vtB + bo[g] + ks * 32);
                    mma_f16(oacc[2 * g    ], a0, a1, a2, a3, b00, b01);
                    mma_f16(oacc[2 * g + 1], a0, a1, a2, a3, b10, b11);
                }
            }
        }
        __syncthreads();
    }

    l0 += __shfl_xor_sync(0xffffffffu, l0, 1);
    l0 += __shfl_xor_sync(0xffffffffu, l0, 2);
    l1 += __shfl_xor_sync(0xffffffffu, l1, 1);
    l1 += __shfl_xor_sync(0xffffffffu, l1, 2);
    const float inv0 = 1.f / l0;
    const float inv1 = 1.f / l1;

    uint32_t* og = (uint32_t*)g_ah +
        ((size_t)(b * SEQ + q0 + w * 16 + lm) * DMODEL + h * HDIM) / 2;
    #pragma unroll
    for (int nt = 0; nt < 8; nt++) {
        og[(nt * 8 + ln) / 2] = pack2(oacc[nt][0] * inv0, oacc[nt][1] * inv0);
        og[(8 * DMODEL + nt * 8 + ln) / 2] = pack2(oacc[nt][2] * inv1, oacc[nt][3] * inv1);
    }
}

// ---------------------------------------------------------------------------
// Launch
// ---------------------------------------------------------------------------
extern "C" void kernel_launch(void* const* d_in, const int* in_sizes, int n_in,
                              void* d_out, int out_size)
{
    (void)in_sizes; (void)n_in; (void)out_size;
    const float* x       = (const float*)d_in[0];
    const float* pos_cos = (const float*)d_in[1];
    const float* pos_sin = (const float*)d_in[2];
    const float* wq_w    = (const float*)d_in[3];
    const float* wq_b    = (const float*)d_in[4];
    const float* wk_w    = (const float*)d_in[5];
    const float* wk_b    = (const float*)d_in[6];
    const float* wv_w    = (const float*)d_in[7];
    const float* wv_b    = (const float*)d_in[8];
    const float* wo_w    = (const float*)d_in[9];
    const float* wo_b    = (const float*)d_in[10];
    float* out = (float*)d_out;

    __half *xh, *whq, *whk, *whv, *who, *qh, *kh, *vh, *ah;
    cudaGetSymbolAddress((void**)&xh,  g_xh);
    cudaGetSymbolAddress((void**)&whq, g_whq);
    cudaGetSymbolAddress((void**)&whk, g_whk);
    cudaGetSymbolAddress((void**)&whv, g_whv);
    cudaGetSymbolAddress((void**)&who, g_who);
    cudaGetSymbolAddress((void**)&qh,  g_qh);
    cudaGetSymbolAddress((void**)&kh,  g_kh);
    cudaGetSymbolAddress((void**)&vh,  g_vh);
    cudaGetSymbolAddress((void**)&ah,  g_ah);

    cudaFuncSetAttribute(gemm_f16_kernel,
                         cudaFuncAttributeMaxDynamicSharedMemorySize, SMEM_DYN);
    cudaFuncSetAttribute(attn_mma_kernel,
                         cudaFuncAttributeMaxDynamicSharedMemorySize, ATTN_SMEM);

    // fp32 -> fp16 conversions (Q weight pre-scaled by 1/sqrt(hd))
    const int X4 = MROWS * DMODEL / 4;
    const int W4 = DMODEL * DMODEL / 4;
    cvt_f2h_kernel<<<1024, 256>>>((const float4*)x, (uint2*)xh, X4, 1.0f);
    dim3 gw(128, 4);
    cvt_w_kernel<<<gw, 256>>>((const float4*)wq_w, (const float4*)wk_w,
                              (const float4*)wv_w, (const float4*)wo_w,
                              (uint2*)whq, (uint2*)whk, (uint2*)whv, (uint2*)who, W4);

    // fused QKV: gridDim.z = 3
    dim3 gq(DMODEL / BN, MROWS / BM, 3);   // (8, 32, 3)
    gemm_f16_kernel<<<gq, 256, SMEM_DYN>>>(xh, whq, whk, whv,
                                           wq_b, wk_b, wv_b,
                                           qh, kh, vh,
                                           0.125f, 1, pos_cos, pos_sin, 0x3);

    dim3 ga(SEQ / 128, NHEAD, BATCH);      // (16, 16, 2)
    attn_mma_kernel<<<ga, 256, ATTN_SMEM>>>();

    // final projection: z = 1 slice
    dim3 go(DMODEL / BN, MROWS / BM, 1);
    gemm_f16_kernel<<<go, 256, SMEM_DYN>>>(ah, who, who, who,
                                           wo_b, wo_b, wo_b,
                                           out, out, out,
                                           1.0f, 0, pos_cos, pos_sin, 0);
}

// round 15
// speedup vs baseline: 3.9334x; 1.1926x over previous
#include <cuda_runtime.h>
#include <cuda_fp16.h>
#include <cstdint>
#include <math.h>

// Problem constants
#define BATCH 2
#define SEQ   2048
#define DMODEL 1024
#define NHEAD 16
#define HDIM  64
#define HALF  32
#define MROWS (BATCH * SEQ)   // 4096

// Scratch (static device globals — allocation-free rule)
__device__ __half g_xh[MROWS * DMODEL];
__device__ __half g_whq[DMODEL * DMODEL];
__device__ __half g_whk[DMODEL * DMODEL];
__device__ __half g_whv[DMODEL * DMODEL];
__device__ __half g_who[DMODEL * DMODEL];
__device__ __half g_qh[MROWS * DMODEL];
__device__ __half g_kh[MROWS * DMODEL];
__device__ __half g_vh[MROWS * DMODEL];
__device__ __half g_ah[MROWS * DMODEL];

__device__ __forceinline__ uint32_t pack2(float a, float b) {
    __half2 h = __floats2half2_rn(a, b);
    return *reinterpret_cast<uint32_t*>(&h);
}

__device__ __forceinline__ void mma_f16(float c[4], uint32_t a0, uint32_t a1,
                                        uint32_t a2, uint32_t a3,
                                        uint32_t b0, uint32_t b1) {
    asm volatile(
        "mma.sync.aligned.m16n8k16.row.col.f32.f16.f16.f32 "
        "{%0,%1,%2,%3}, {%4,%5,%6,%7}, {%8,%9}, {%0,%1,%2,%3};"
        : "+f"(c[0]), "+f"(c[1]), "+f"(c[2]), "+f"(c[3])
        : "r"(a0), "r"(a1), "r"(a2), "r"(a3), "r"(b0), "r"(b1));
}

__device__ __forceinline__ void ldmx4(uint32_t& r0, uint32_t& r1,
                                      uint32_t& r2, uint32_t& r3, uint32_t addr) {
    asm volatile("ldmatrix.sync.aligned.m8n8.x4.shared.b16 {%0,%1,%2,%3}, [%4];"
                 : "=r"(r0), "=r"(r1), "=r"(r2), "=r"(r3) : "r"(addr));
}

__device__ __forceinline__ void ldmx4t(uint32_t& r0, uint32_t& r1,
                                       uint32_t& r2, uint32_t& r3, uint32_t addr) {
    asm volatile("ldmatrix.sync.aligned.m8n8.x4.trans.shared.b16 {%0,%1,%2,%3}, [%4];"
                 : "=r"(r0), "=r"(r1), "=r"(r2), "=r"(r3) : "r"(addr));
}

__device__ __forceinline__ uint32_t smem_u32(const void* p) {
    uint32_t a;
    asm("{ .reg .u64 t; cvta.to.shared.u64 t, %1; cvt.u32.u64 %0, t; }"
        : "=r"(a) : "l"(p));
    return a;
}

__device__ __forceinline__ void cp16(uint32_t dst, const void* src) {
    asm volatile("cp.async.cg.shared.global [%0], [%1], 16;"
                 :: "r"(dst), "l"(src));
}
#define CP_COMMIT() asm volatile("cp.async.commit_group;" ::: "memory")
#define CP_WAIT1()  asm volatile("cp.async.wait_group 1;"  ::: "memory")

// ---------------------------------------------------------------------------
// fp32 -> fp16 conversions
// ---------------------------------------------------------------------------
__global__ void cvt_f2h_kernel(const float4* __restrict__ in,
                               uint2* __restrict__ out, int n4, float scale)
{
    for (int i = blockIdx.x * blockDim.x + threadIdx.x; i < n4;
         i += gridDim.x * blockDim.x) {
        float4 v = in[i];
        uint2 o;
        o.x = pack2(v.x * scale, v.y * scale);
        o.y = pack2(v.z * scale, v.w * scale);
        out[i] = o;
    }
}

__global__ void cvt_w_kernel(const float4* __restrict__ w0, const float4* __restrict__ w1,
                             const float4* __restrict__ w2, const float4* __restrict__ w3,
                             uint2* __restrict__ o0, uint2* __restrict__ o1,
                             uint2* __restrict__ o2, uint2* __restrict__ o3, int n4)
{
    const int which = blockIdx.y;
    const float4* in = which == 0 ? w0 : which == 1 ? w1 : which == 2 ? w2 : w3;
    uint2* out       = which == 0 ? o0 : which == 1 ? o1 : which == 2 ? o2 : o3;
    const float scale = which == 0 ? 0.125f : 1.0f;
    for (int i = blockIdx.x * blockDim.x + threadIdx.x; i < n4;
         i += gridDim.x * blockDim.x) {
        float4 v = in[i];
        uint2 o;
        o.x = pack2(v.x * scale, v.y * scale);
        o.y = pack2(v.z * scale, v.w * scale);
        out[i] = o;
    }
}

// ---------------------------------------------------------------------------
// fp16 GEMM, cp.async 3-stage pipeline + ldmatrix, KC=64 (unchanged R14).
// ---------------------------------------------------------------------------
#define BM 128
#define BN 128
#define KC 64
#define NT (DMODEL / KC)       // 16
#define GST 36
#define GTILEW (128 * GST)
#define NSTAGE 3
#define SMEM_DYN (NSTAGE * 2 * GTILEW * 4)   // 110592 bytes

__global__ void __launch_bounds__(256, 2)
gemm_f16_kernel(const __half* __restrict__ A,
                const __half* __restrict__ W0, const __half* __restrict__ W1,
                const __half* __restrict__ W2,
                const float* __restrict__ b0, const float* __restrict__ b1,
                const float* __restrict__ b2,
                void* __restrict__ o0, void* __restrict__ o1, void* __restrict__ o2,
                float bscale0,
                int outHalf,
                const float* __restrict__ cosb,
                const float* __restrict__ sinb,
                int ropeMask)
{
    extern __shared__ uint32_t su[];
    const uint32_t sbase = smem_u32(su);

    const int z = blockIdx.z;
    const __half* W  = z == 0 ? W0 : z == 1 ? W1 : W2;
    const float* bias = z == 0 ? b0 : z == 1 ? b1 : b2;
    void* Cout = z == 0 ? o0 : z == 1 ? o1 : o2;
    const float bscale = z == 0 ? bscale0 : 1.0f;
    const int applyRope = (ropeMask >> z) & 1;

    const int tid = threadIdx.x;
    const int wid = tid >> 5;
    const int lid = tid & 31;
    const int wm = (wid & 1) * 64;
    const int wn = (wid >> 1) * 32;
    const int m0 = blockIdx.y * BM;
    const int n0 = blockIdx.x * BN;

    const __half* Abase = A + (size_t)m0 * DMODEL;
    const __half* Wbase = W + (size_t)n0 * DMODEL;

    #define CPLOAD(kt, stg) do {                                               \
        const __half* _as = Abase + (kt) * KC;                                 \
        const __half* _ws = Wbase + (kt) * KC;                                 \
        const uint32_t _ab = sbase + (2 * (stg)) * GTILEW * 4;                 \
        const uint32_t _bb = _ab + GTILEW * 4;                                 \
        _Pragma("unroll")                                                      \
        for (int _i = 0; _i < 4; _i++) {                                       \
            int _s = tid + _i * 256;                                           \
            int _r = _s >> 3, _sg = (_s & 7) * 4;                              \
            cp16(_ab + (_r * GST + _sg) * 4, _as + (size_t)_r * DMODEL + _sg * 2); \
            cp16(_bb + (_r * GST + _sg) * 4, _ws + (size_t)_r * DMODEL + _sg * 2); \
        }                                                                      \
    } while (0)

    float acc[4][4][4];
    #pragma unroll
    for (int i = 0; i < 4; i++)
        #pragma unroll
        for (int j = 0; j < 4; j++)
            #pragma unroll
            for (int r = 0; r < 4; r++) acc[i][j][r] = 0.f;

    uint32_t aoff[4], boff[2];
    #pragma unroll
    for (int mf = 0; mf < 4; mf++)
        aoff[mf] = ((wm + mf * 16 + (lid & 15)) * GST + (lid >> 4) * 4) * 4;
    #pragma unroll
    for (int p = 0; p < 2; p++)
        boff[p] = ((wn + p * 16 + (lid & 7) + ((lid >> 4) & 1) * 8) * GST
                   + ((lid >> 3) & 1) * 4) * 4;

    CPLOAD(0, 0); CP_COMMIT();
    CPLOAD(1, 1); CP_COMMIT();

    for (int kt = 0; kt < NT; kt++) {
        CP_WAIT1();
        __syncthreads();
        if (kt + 2 < NT) CPLOAD(kt + 2, (kt + 2) % NSTAGE);
        CP_COMMIT();

        const uint32_t aB = sbase + (2 * (kt % NSTAGE)) * GTILEW * 4;
        const uint32_t bB = aB + GTILEW * 4;
        #pragma unroll
        for (int ks = 0; ks < 4; ks++) {
            uint32_t af[4][4];
            #pragma unroll
            for (int mf = 0; mf < 4; mf++)
                ldmx4(af[mf][0], af[mf][1], af[mf][2], af[mf][3],
                      aB + aoff[mf] + ks * 32);
            #pragma unroll
            for (int p = 0; p < 2; p++) {
                uint32_t b00, b01, b10, b11;
                ldmx4(b00, b01, b10, b11, bB + boff[p] + ks * 32);
                #pragma unroll
                for (int mf = 0; mf < 4; mf++) {
                    mma_f16(acc[mf][2 * p    ], af[mf][0], af[mf][1], af[mf][2], af[mf][3], b00, b01);
                    mma_f16(acc[mf][2 * p + 1], af[mf][0], af[mf][1], af[mf][2], af[mf][3], b10, b11);
                }
            }
        }
    }

    const int lm = lid >> 2;
    const int ln = (lid & 3) * 2;
    #pragma unroll
    for (int mf = 0; mf < 4; mf++) {
        #pragma unroll
        for (int half_ = 0; half_ < 2; half_++) {
            const int m = m0 + wm + mf * 16 + lm + half_ * 8;
            const int spos = m & (SEQ - 1);
            #pragma unroll
            for (int nf = 0; nf < 4; nf++) {
                const int n = n0 + wn + nf * 8 + ln;
                float v0 = acc[mf][nf][half_ * 2 + 0] + bias[n] * bscale;
                float v1 = acc[mf][nf][half_ * 2 + 1] + bias[n + 1] * bscale;
                if (applyRope) {
                    const int fi = (n & (HDIM - 1)) >> 1;
                    const float cc = cosb[spos * HALF + fi];
                    const float ss = sinb[spos * HALF + fi];
                    const float t0 = v0 * cc - v1 * ss;
                    const float t1 = v0 * ss + v1 * cc;
                    v0 = t0; v1 = t1;
                }
                if (outHalf) {
                    uint32_t* crow = (uint32_t*)Cout + (size_t)m * (DMODEL / 2);
                    crow[n / 2] = pack2(v0, v1);
                } else {
                    float* crow = (float*)Cout + (size_t)m * DMODEL;
                    float2 st; st.x = v0; st.y = v1;
                    *(float2*)(crow + n) = st;
                }
            }
        }
    }
}

// ---------------------------------------------------------------------------
// fp16 flash attention: register-resident P, ldmatrix.trans V,
// cp.async double-buffered K/V tiles. 2 CTAs/SM.
// ---------------------------------------------------------------------------
#define ASTW 36
#define KTW (64 * ASTW)                 // 2304 words
#define VTW (64 * ASTW)
#define KVSTGW (KTW + VTW)              // 4608 words per stage
#define QTW (128 * ASTW)
#define ATTN_SMEM ((2 * KVSTGW + QTW) * 4)   // 55296 bytes

__global__ void __launch_bounds__(256, 2)
attn_mma_kernel()
{
    extern __shared__ uint32_t su[];
    const uint32_t sbase = smem_u32(su);
    uint32_t* qt = su + 2 * KVSTGW;
    const uint32_t qtB = sbase + 2 * KVSTGW * 4;

    const int b  = blockIdx.z;
    const int h  = blockIdx.y;
    const int q0 = ((int)gridDim.x - 1 - (int)blockIdx.x) * 128;  // heavy first
    const int tid = threadIdx.x;
    const int w   = tid >> 5;
    const int lid = tid & 31;
    const int lm = lid >> 2;
    const int lk = lid & 3;
    const int ln = lk * 2;

    // ldmatrix offsets
    const uint32_t qoff =
        ((w * 16 + (lid & 15)) * ASTW + (lid >> 4) * 4) * 4;            // Q A-frag
    uint32_t ko[4];
    #pragma unroll
    for (int g = 0; g < 4; g++)
        ko[g] = ((g * 16 + (lid & 7) + ((lid >> 4) & 1) * 8) * ASTW
                 + ((lid >> 3) & 1) * 4) * 4;                            // K B-frag
    uint32_t vo[4];
    #pragma unroll
    for (int g = 0; g < 4; g++)
        vo[g] = (((lid & 7) + ((lid >> 3) & 1) * 8) * ASTW) * 4
                + (g * 16 + ((lid >> 4) & 1) * 8) * 2;                   // V^T B-frag (trans)

    const __half* kg = g_kh + ((size_t)(b * SEQ) * DMODEL + h * HDIM);
    const __half* vg = g_vh + ((size_t)(b * SEQ) * DMODEL + h * HDIM);

    // cp.async K/V tile staging: 512 segs each, 2+2 per thread
    #define CPKV(t, s) do {                                                    \
        const __half* _kb = kg + (size_t)((t) * 64) * DMODEL;                  \
        const __half* _vb = vg + (size_t)((t) * 64) * DMODEL;                  \
        const uint32_t _kB = sbase + (s) * KVSTGW * 4;                         \
        const uint32_t _vB = _kB + KTW * 4;                                    \
        _Pragma("unroll")                                                      \
        for (int _i = 0; _i < 2; _i++) {                                       \
            int _s = tid + _i * 256;                                           \
            int _r = _s >> 3, _sg = (_s & 7) * 4;                              \
            cp16(_kB + (_r * ASTW + _sg) * 4, _kb + (size_t)_r * DMODEL + _sg * 2); \
            cp16(_vB + (_r * ASTW + _sg) * 4, _vb + (size_t)_r * DMODEL + _sg * 2); \
        }                                                                      \
    } while (0)

    const int ntiles = q0 / 64 + 2;

    // prologue: stage Q + first two KV tiles
    CPKV(0, 0); CP_COMMIT();
    if (ntiles > 1) CPKV(1, 1);
    CP_COMMIT();

    const __half* qg = g_qh + ((size_t)(b * SEQ + q0) * DMODEL + h * HDIM);
    #pragma unroll
    for (int i = 0; i < 4; i++) {
        int s = tid + i * 256;
        int row = s >> 3;
        int sg  = (s & 7) * 4;
        uint4 v = *(const uint4*)(qg + (size_t)row * DMODEL + sg * 2);
        *(uint4*)(qt + row * ASTW + sg) = v;
    }
    __syncthreads();

    uint32_t aq[4][4];
    #pragma unroll
    for (int ks = 0; ks < 4; ks++)
        ldmx4(aq[ks][0], aq[ks][1], aq[ks][2], aq[ks][3], qtB + qoff + ks * 32);

    float m0 = -1e30f, m1 = -1e30f, l0 = 0.f, l1 = 0.f;
    float oacc[8][4];
    #pragma unroll
    for (int nt = 0; nt < 8; nt++)
        #pragma unroll
        for (int r = 0; r < 4; r++) oacc[nt][r] = 0.f;

    for (int t = 0; t < ntiles; t++) {
        CP_WAIT1();
        __syncthreads();

        const uint32_t kB = sbase + (t & 1) * KVSTGW * 4;
        const uint32_t vB = kB + KTW * 4;

        const bool active = !(w < 4 && t == ntiles - 1);   // warp-uniform
        if (active) {
            // ---- S = Q K^T ----
            float sacc[8][4];
            #pragma unroll
            for (int nt = 0; nt < 8; nt++)
                #pragma unroll
                for (int r = 0; r < 4; r++) sacc[nt][r] = 0.f;

            #pragma unroll
            for (int ks = 0; ks < 4; ks++) {
                #pragma unroll
                for (int g = 0; g < 4; g++) {
                    uint32_t b00, b01, b10, b11;
                    ldmx4(b00, b01, b10, b11, kB + ko[g] + ks * 32);
                    mma_f16(sacc[2 * g    ], aq[ks][0], aq[ks][1], aq[ks][2], aq[ks][3], b00, b01);
                    mma_f16(sacc[2 * g + 1], aq[ks][0], aq[ks][1], aq[ks][2], aq[ks][3], b10, b11);
                }
            }

            // ---- causal mask (last two tiles only) ----
            if (t >= ntiles - 2) {
                const int kv0 = t * 64;
                const int rel0 = q0 + w * 16 + lm - kv0;
                const int rel1 = rel0 + 8;
                #pragma unroll
                for (int nt = 0; nt < 8; nt++) {
                    const int c0 = nt * 8 + ln;
                    if (c0     > rel0) sacc[nt][0] = -1e30f;
                    if (c0 + 1 > rel0) sacc[nt][1] = -1e30f;
                    if (c0     > rel1) sacc[nt][2] = -1e30f;
                    if (c0 + 1 > rel1) sacc[nt][3] = -1e30f;
                }
            }

            // ---- online softmax ----
            float rm0 = -1e30f, rm1 = -1e30f;
            #pragma unroll
            for (int nt = 0; nt < 8; nt++) {
                rm0 = fmaxf(rm0, fmaxf(sacc[nt][0], sacc[nt][1]));
                rm1 = fmaxf(rm1, fmaxf(sacc[nt][2], sacc[nt][3]));
            }
            rm0 = fmaxf(rm0, __shfl_xor_sync(0xffffffffu, rm0, 1));
            rm0 = fmaxf(rm0, __shfl_xor_sync(0xffffffffu, rm0, 2));
            rm1 = fmaxf(rm1, __shfl_xor_sync(0xffffffffu, rm1, 1));
            rm1 = fmaxf(rm1, __shfl_xor_sync(0xffffffffu, rm1, 2));

            const float mn0 = fmaxf(m0, rm0);
            const float mn1 = fmaxf(m1, rm1);
            const float sc0 = __expf(m0 - mn0);
            const float sc1 = __expf(m1 - mn1);
            m0 = mn0; m1 = mn1;
            l0 *= sc0; l1 *= sc1;
            #pragma unroll
            for (int nt = 0; nt < 8; nt++) {
                oacc[nt][0] *= sc0; oacc[nt][1] *= sc0;
                oacc[nt][2] *= sc1; oacc[nt][3] *= sc1;
            }

            // ---- P in registers (C-frag of S == A-frag of PV) + O += P V ----
            #pragma unroll
            for (int ks = 0; ks < 4; ks++) {
                const float pe0 = __expf(sacc[2 * ks][0] - m0);
                const float pe1 = __expf(sacc[2 * ks][1] - m0);
                const float pe2 = __expf(sacc[2 * ks][2] - m1);
                const float pe3 = __expf(sacc[2 * ks][3] - m1);
                const float pf0 = __expf(sacc[2 * ks + 1][0] - m0);
                const float pf1 = __expf(sacc[2 * ks + 1][1] - m0);
                const float pf2 = __expf(sacc[2 * ks + 1][2] - m1);
                const float pf3 = __expf(sacc[2 * ks + 1][3] - m1);
                l0 += pe0 + pe1 + pf0 + pf1;
                l1 += pe2 + pe3 + pf2 + pf3;
                const uint32_t a0 = pack2(pe0, pe1);
                const uint32_t a1 = pack2(pe2, pe3);
                const uint32_t a2 = pack2(pf0, pf1);
                const uint32_t a3 = pack2(pf2, pf3);
                #pragma unroll
                for (int g = 0; g < 4; g++) {
                    uint32_t b00, b01, b10, b11;
                    ldmx4t(b00, b01, b10, b11, vB + vo[g] + ks * 16 * ASTW * 4);
                    mma_f16(oacc[2 * g    ], a0, a1, a2, a3, b00, b01);
                    mma_f16(oacc[2 * g + 1], a0, a1, a2, a3, b10, b11);
                }
            }
        }
        __syncthreads();
        if (t + 2 < ntiles) CPKV(t + 2, t & 1);
        CP_COMMIT();
    }

    // ---- finalize: write fp16 to g_ah ----
    l0 += __shfl_xor_sync(0xffffffffu, l0, 1);
    l0 += __shfl_xor_sync(0xffffffffu, l0, 2);
    l1 += __shfl_xor_sync(0xffffffffu, l1, 1);
    l1 += __shfl_xor_sync(0xffffffffu, l1, 2);
    const float inv0 = 1.f / l0;
    const float inv1 = 1.f / l1;

    uint32_t* og = (uint32_t*)g_ah +
        ((size_t)(b * SEQ + q0 + w * 16 + lm) * DMODEL + h * HDIM) / 2;
    #pragma unroll
    for (int nt = 0; nt < 8; nt++) {
        og[(nt * 8 + ln) / 2] = pack2(oacc[nt][0] * inv0, oacc[nt][1] * inv0);
        og[(8 * DMODEL + nt * 8 + ln) / 2] = pack2(oacc[nt][2] * inv1, oacc[nt][3] * inv1);
    }
}

// ---------------------------------------------------------------------------
// Launch
// ---------------------------------------------------------------------------
extern "C" void kernel_launch(void* const* d_in, const int* in_sizes, int n_in,
                              void* d_out, int out_size)
{
    (void)in_sizes; (void)n_in; (void)out_size;
    const float* x       = (const float*)d_in[0];
    const float* pos_cos = (const float*)d_in[1];
    const float* pos_sin = (const float*)d_in[2];
    const float* wq_w    = (const float*)d_in[3];
    const float* wq_b    = (const float*)d_in[4];
    const float* wk_w    = (const float*)d_in[5];
    const float* wk_b    = (const float*)d_in[6];
    const float* wv_w    = (const float*)d_in[7];
    const float* wv_b    = (const float*)d_in[8];
    const float* wo_w    = (const float*)d_in[9];
    const float* wo_b    = (const float*)d_in[10];
    float* out = (float*)d_out;

    __half *xh, *whq, *whk, *whv, *who, *qh, *kh, *vh, *ah;
    cudaGetSymbolAddress((void**)&xh,  g_xh);
    cudaGetSymbolAddress((void**)&whq, g_whq);
    cudaGetSymbolAddress((void**)&whk, g_whk);
    cudaGetSymbolAddress((void**)&whv, g_whv);
    cudaGetSymbolAddress((void**)&who, g_who);
    cudaGetSymbolAddress((void**)&qh,  g_qh);
    cudaGetSymbolAddress((void**)&kh,  g_kh);
    cudaGetSymbolAddress((void**)&vh,  g_vh);
    cudaGetSymbolAddress((void**)&ah,  g_ah);

    cudaFuncSetAttribute(gemm_f16_kernel,
                         cudaFuncAttributeMaxDynamicSharedMemorySize, SMEM_DYN);
    cudaFuncSetAttribute(attn_mma_kernel,
                         cudaFuncAttributeMaxDynamicSharedMemorySize, ATTN_SMEM);

    // fp32 -> fp16 conversions (Q weight pre-scaled by 1/sqrt(hd))
    const int X4 = MROWS * DMODEL / 4;
    const int W4 = DMODEL * DMODEL / 4;
    cvt_f2h_kernel<<<1024, 256>>>((const float4*)x, (uint2*)xh, X4, 1.0f);
    dim3 gw(128, 4);
    cvt_w_kernel<<<gw, 256>>>((const float4*)wq_w, (const float4*)wk_w,
                              (const float4*)wv_w, (const float4*)wo_w,
                              (uint2*)whq, (uint2*)whk, (uint2*)whv, (uint2*)who, W4);

    // fused QKV: gridDim.z = 3
    dim3 gq(DMODEL / BN, MROWS / BM, 3);   // (8, 32, 3)
    gemm_f16_kernel<<<gq, 256, SMEM_DYN>>>(xh, whq, whk, whv,
                                           wq_b, wk_b, wv_b,
                                           qh, kh, vh,
                                           0.125f, 1, pos_cos, pos_sin, 0x3);

    dim3 ga(SEQ / 128, NHEAD, BATCH);      // (16, 16, 2)
    attn_mma_kernel<<<ga, 256, ATTN_SMEM>>>();

    // final projection
    dim3 go(DMODEL / BN, MROWS / BM, 1);
    gemm_f16_kernel<<<go, 256, SMEM_DYN>>>(ah, who, who, who,
                                           wo_b, wo_b, wo_b,
                                           out, out, out,
                                           1.0f, 0, pos_cos, pos_sin, 0);
}

// round 16
// speedup vs baseline: 3.9727x; 1.0100x over previous
#include <cuda_runtime.h>
#include <cuda_fp16.h>
#include <cstdint>
#include <math.h>

// Problem constants
#define BATCH 2
#define SEQ   2048
#define DMODEL 1024
#define NHEAD 16
#define HDIM  64
#define HALF  32
#define MROWS (BATCH * SEQ)   // 4096
#define LOG2E 1.44269504088896f

// Scratch (static device globals — allocation-free rule)
__device__ __half g_xh[MROWS * DMODEL];
__device__ __half g_whq[DMODEL * DMODEL];
__device__ __half g_whk[DMODEL * DMODEL];
__device__ __half g_whv[DMODEL * DMODEL];
__device__ __half g_who[DMODEL * DMODEL];
__device__ __half g_qh[MROWS * DMODEL];
__device__ __half g_kh[MROWS * DMODEL];
__device__ __half g_vh[MROWS * DMODEL];
__device__ __half g_ah[MROWS * DMODEL];

__device__ __forceinline__ uint32_t pack2(float a, float b) {
    __half2 h = __floats2half2_rn(a, b);
    return *reinterpret_cast<uint32_t*>(&h);
}

__device__ __forceinline__ float ex2f(float x) {
    float r;
    asm("ex2.approx.f32 %0, %1;" : "=f"(r) : "f"(x));
    return r;
}

__device__ __forceinline__ void mma_f16(float c[4], uint32_t a0, uint32_t a1,
                                        uint32_t a2, uint32_t a3,
                                        uint32_t b0, uint32_t b1) {
    asm volatile(
        "mma.sync.aligned.m16n8k16.row.col.f32.f16.f16.f32 "
        "{%0,%1,%2,%3}, {%4,%5,%6,%7}, {%8,%9}, {%0,%1,%2,%3};"
        : "+f"(c[0]), "+f"(c[1]), "+f"(c[2]), "+f"(c[3])
        : "r"(a0), "r"(a1), "r"(a2), "r"(a3), "r"(b0), "r"(b1));
}

__device__ __forceinline__ void ldmx4(uint32_t& r0, uint32_t& r1,
                                      uint32_t& r2, uint32_t& r3, uint32_t addr) {
    asm volatile("ldmatrix.sync.aligned.m8n8.x4.shared.b16 {%0,%1,%2,%3}, [%4];"
                 : "=r"(r0), "=r"(r1), "=r"(r2), "=r"(r3) : "r"(addr));
}

__device__ __forceinline__ void ldmx4t(uint32_t& r0, uint32_t& r1,
                                       uint32_t& r2, uint32_t& r3, uint32_t addr) {
    asm volatile("ldmatrix.sync.aligned.m8n8.x4.trans.shared.b16 {%0,%1,%2,%3}, [%4];"
                 : "=r"(r0), "=r"(r1), "=r"(r2), "=r"(r3) : "r"(addr));
}

__device__ __forceinline__ uint32_t smem_u32(const void* p) {
    uint32_t a;
    asm("{ .reg .u64 t; cvta.to.shared.u64 t, %1; cvt.u32.u64 %0, t; }"
        : "=r"(a) : "l"(p));
    return a;
}

__device__ __forceinline__ void cp16(uint32_t dst, const void* src) {
    asm volatile("cp.async.cg.shared.global [%0], [%1], 16;"
                 :: "r"(dst), "l"(src));
}
#define CP_COMMIT() asm volatile("cp.async.commit_group;" ::: "memory")
#define CP_WAIT1()  asm volatile("cp.async.wait_group 1;"  ::: "memory")

// ---------------------------------------------------------------------------
// merged fp32 -> fp16 conversion: blockIdx.y picks job (0=x, 1..4=weights).
// Q weight pre-scaled by 0.125 * log2(e) (softmax in log2 domain).
// ---------------------------------------------------------------------------
__global__ void cvt_all_kernel(const float4* __restrict__ x,
                               const float4* __restrict__ wq,
                               const float4* __restrict__ wk,
                               const float4* __restrict__ wv,
                               const float4* __restrict__ wo,
                               uint2* __restrict__ xo, uint2* __restrict__ qo,
                               uint2* __restrict__ ko, uint2* __restrict__ vo,
                               uint2* __restrict__ oo, int xn4, int wn4)
{
    const int j = blockIdx.y;
    const float4* in = j == 0 ? x : j == 1 ? wq : j == 2 ? wk : j == 3 ? wv : wo;
    uint2* out       = j == 0 ? xo : j == 1 ? qo : j == 2 ? ko : j == 3 ? vo : oo;
    const int n4     = j == 0 ? xn4 : wn4;
    const float scale = j == 1 ? 0.125f * LOG2E : 1.0f;
    for (int i = blockIdx.x * blockDim.x + threadIdx.x; i < n4;
         i += gridDim.x * blockDim.x) {
        float4 v = in[i];
        uint2 o;
        o.x = pack2(v.x * scale, v.y * scale);
        o.y = pack2(v.z * scale, v.w * scale);
        out[i] = o;
    }
}

// ---------------------------------------------------------------------------
// fp16 GEMM, cp.async 3-stage pipeline + ldmatrix, KC=64 (unchanged R14).
// ---------------------------------------------------------------------------
#define BM 128
#define BN 128
#define KC 64
#define NT (DMODEL / KC)       // 16
#define GST 36
#define GTILEW (128 * GST)
#define NSTAGE 3
#define SMEM_DYN (NSTAGE * 2 * GTILEW * 4)   // 110592 bytes

__global__ void __launch_bounds__(256, 2)
gemm_f16_kernel(const __half* __restrict__ A,
                const __half* __restrict__ W0, const __half* __restrict__ W1,
                const __half* __restrict__ W2,
                const float* __restrict__ b0, const float* __restrict__ b1,
                const float* __restrict__ b2,
                void* __restrict__ o0, void* __restrict__ o1, void* __restrict__ o2,
                float bscale0,
                int outHalf,
                const float* __restrict__ cosb,
                const float* __restrict__ sinb,
                int ropeMask)
{
    extern __shared__ uint32_t su[];
    const uint32_t sbase = smem_u32(su);

    const int z = blockIdx.z;
    const __half* W  = z == 0 ? W0 : z == 1 ? W1 : W2;
    const float* bias = z == 0 ? b0 : z == 1 ? b1 : b2;
    void* Cout = z == 0 ? o0 : z == 1 ? o1 : o2;
    const float bscale = z == 0 ? bscale0 : 1.0f;
    const int applyRope = (ropeMask >> z) & 1;

    const int tid = threadIdx.x;
    const int wid = tid >> 5;
    const int lid = tid & 31;
    const int wm = (wid & 1) * 64;
    const int wn = (wid >> 1) * 32;
    const int m0 = blockIdx.y * BM;
    const int n0 = blockIdx.x * BN;

    const __half* Abase = A + (size_t)m0 * DMODEL;
    const __half* Wbase = W + (size_t)n0 * DMODEL;

    #define CPLOAD(kt, stg) do {                                               \
        const __half* _as = Abase + (kt) * KC;                                 \
        const __half* _ws = Wbase + (kt) * KC;                                 \
        const uint32_t _ab = sbase + (2 * (stg)) * GTILEW * 4;                 \
        const uint32_t _bb = _ab + GTILEW * 4;                                 \
        _Pragma("unroll")                                                      \
        for (int _i = 0; _i < 4; _i++) {                                       \
            int _s = tid + _i * 256;                                           \
            int _r = _s >> 3, _sg = (_s & 7) * 4;                              \
            cp16(_ab + (_r * GST + _sg) * 4, _as + (size_t)_r * DMODEL + _sg * 2); \
            cp16(_bb + (_r * GST + _sg) * 4, _ws + (size_t)_r * DMODEL + _sg * 2); \
        }                                                                      \
    } while (0)

    float acc[4][4][4];
    #pragma unroll
    for (int i = 0; i < 4; i++)
        #pragma unroll
        for (int j = 0; j < 4; j++)
            #pragma unroll
            for (int r = 0; r < 4; r++) acc[i][j][r] = 0.f;

    uint32_t aoff[4], boff[2];
    #pragma unroll
    for (int mf = 0; mf < 4; mf++)
        aoff[mf] = ((wm + mf * 16 + (lid & 15)) * GST + (lid >> 4) * 4) * 4;
    #pragma unroll
    for (int p = 0; p < 2; p++)
        boff[p] = ((wn + p * 16 + (lid & 7) + ((lid >> 4) & 1) * 8) * GST
                   + ((lid >> 3) & 1) * 4) * 4;

    CPLOAD(0, 0); CP_COMMIT();
    CPLOAD(1, 1); CP_COMMIT();

    for (int kt = 0; kt < NT; kt++) {
        CP_WAIT1();
        __syncthreads();
        if (kt + 2 < NT) CPLOAD(kt + 2, (kt + 2) % NSTAGE);
        CP_COMMIT();

        const uint32_t aB = sbase + (2 * (kt % NSTAGE)) * GTILEW * 4;
        const uint32_t bB = aB + GTILEW * 4;
        #pragma unroll
        for (int ks = 0; ks < 4; ks++) {
            uint32_t af[4][4];
            #pragma unroll
            for (int mf = 0; mf < 4; mf++)
                ldmx4(af[mf][0], af[mf][1], af[mf][2], af[mf][3],
                      aB + aoff[mf] + ks * 32);
            #pragma unroll
            for (int p = 0; p < 2; p++) {
                uint32_t b00, b01, b10, b11;
                ldmx4(b00, b01, b10, b11, bB + boff[p] + ks * 32);
                #pragma unroll
                for (int mf = 0; mf < 4; mf++) {
                    mma_f16(acc[mf][2 * p    ], af[mf][0], af[mf][1], af[mf][2], af[mf][3], b00, b01);
                    mma_f16(acc[mf][2 * p + 1], af[mf][0], af[mf][1], af[mf][2], af[mf][3], b10, b11);
                }
            }
        }
    }

    const int lm = lid >> 2;
    const int ln = (lid & 3) * 2;
    #pragma unroll
    for (int mf = 0; mf < 4; mf++) {
        #pragma unroll
        for (int half_ = 0; half_ < 2; half_++) {
            const int m = m0 + wm + mf * 16 + lm + half_ * 8;
            const int spos = m & (SEQ - 1);
            #pragma unroll
            for (int nf = 0; nf < 4; nf++) {
                const int n = n0 + wn + nf * 8 + ln;
                float v0 = acc[mf][nf][half_ * 2 + 0] + bias[n] * bscale;
                float v1 = acc[mf][nf][half_ * 2 + 1] + bias[n + 1] * bscale;
                if (applyRope) {
                    const int fi = (n & (HDIM - 1)) >> 1;
                    const float cc = cosb[spos * HALF + fi];
                    const float ss = sinb[spos * HALF + fi];
                    const float t0 = v0 * cc - v1 * ss;
                    const float t1 = v0 * ss + v1 * cc;
                    v0 = t0; v1 = t1;
                }
                if (outHalf) {
                    uint32_t* crow = (uint32_t*)Cout + (size_t)m * (DMODEL / 2);
                    crow[n / 2] = pack2(v0, v1);
                } else {
                    float* crow = (float*)Cout + (size_t)m * DMODEL;
                    float2 st; st.x = v0; st.y = v1;
                    *(float2*)(crow + n) = st;
                }
            }
        }
    }
}

// ---------------------------------------------------------------------------
// fp16 flash attention: register P, ldmatrix.trans V, 3-stage cp.async KV,
// ONE barrier per tile, softmax in log2 domain (ex2.approx). 2 CTAs/SM.
// ---------------------------------------------------------------------------
#define ASTW 36
#define KTW (64 * ASTW)                 // 2304 words
#define VTW (64 * ASTW)
#define KVSTGW (KTW + VTW)              // 4608 words per stage
#define QTW (128 * ASTW)
#define ATTN_SMEM ((3 * KVSTGW + QTW) * 4)   // 73728 bytes

__global__ void __launch_bounds__(256, 2)
attn_mma_kernel()
{
    extern __shared__ uint32_t su[];
    const uint32_t sbase = smem_u32(su);
    uint32_t* qt = su + 3 * KVSTGW;
    const uint32_t qtB = sbase + 3 * KVSTGW * 4;

    const int b  = blockIdx.z;
    const int h  = blockIdx.y;
    const int q0 = ((int)gridDim.x - 1 - (int)blockIdx.x) * 128;  // heavy first
    const int tid = threadIdx.x;
    const int w   = tid >> 5;
    const int lid = tid & 31;
    const int lm = lid >> 2;
    const int lk = lid & 3;
    const int ln = lk * 2;

    const uint32_t qoff =
        ((w * 16 + (lid & 15)) * ASTW + (lid >> 4) * 4) * 4;            // Q A-frag
    uint32_t ko[4];
    #pragma unroll
    for (int g = 0; g < 4; g++)
        ko[g] = ((g * 16 + (lid & 7) + ((lid >> 4) & 1) * 8) * ASTW
                 + ((lid >> 3) & 1) * 4) * 4;                            // K B-frag
    uint32_t vo[4];
    #pragma unroll
    for (int g = 0; g < 4; g++)
        vo[g] = (((lid & 7) + ((lid >> 3) & 1) * 8) * ASTW) * 4
                + (g * 16 + ((lid >> 4) & 1) * 8) * 2;                   // V^T B-frag

    const __half* kg = g_kh + ((size_t)(b * SEQ) * DMODEL + h * HDIM);
    const __half* vg = g_vh + ((size_t)(b * SEQ) * DMODEL + h * HDIM);

    #define CPKV(t, s) do {                                                    \
        const __half* _kb = kg + (size_t)((t) * 64) * DMODEL;                  \
        const __half* _vb = vg + (size_t)((t) * 64) * DMODEL;                  \
        const uint32_t _kB = sbase + (s) * KVSTGW * 4;                         \
        const uint32_t _vB = _kB + KTW * 4;                                    \
        _Pragma("unroll")                                                      \
        for (int _i = 0; _i < 2; _i++) {                                       \
            int _s = tid + _i * 256;                                           \
            int _r = _s >> 3, _sg = (_s & 7) * 4;                              \
            cp16(_kB + (_r * ASTW + _sg) * 4, _kb + (size_t)_r * DMODEL + _sg * 2); \
            cp16(_vB + (_r * ASTW + _sg) * 4, _vb + (size_t)_r * DMODEL + _sg * 2); \
        }                                                                      \
    } while (0)

    const int ntiles = q0 / 64 + 2;

    CPKV(0, 0); CP_COMMIT();
    CPKV(1, 1); CP_COMMIT();

    const __half* qg = g_qh + ((size_t)(b * SEQ + q0) * DMODEL + h * HDIM);
    #pragma unroll
    for (int i = 0; i < 4; i++) {
        int s = tid + i * 256;
        int row = s >> 3;
        int sg  = (s & 7) * 4;
        uint4 v = *(const uint4*)(qg + (size_t)row * DMODEL + sg * 2);
        *(uint4*)(qt + row * ASTW + sg) = v;
    }
    __syncthreads();

    uint32_t aq[4][4];
    #pragma unroll
    for (int ks = 0; ks < 4; ks++)
        ldmx4(aq[ks][0], aq[ks][1], aq[ks][2], aq[ks][3], qtB + qoff + ks * 32);

    float m0 = -1e30f, m1 = -1e30f, l0 = 0.f, l1 = 0.f;
    float oacc[8][4];
    #pragma unroll
    for (int nt = 0; nt < 8; nt++)
        #pragma unroll
        for (int r = 0; r < 4; r++) oacc[nt][r] = 0.f;

    for (int t = 0; t < ntiles; t++) {
        CP_WAIT1();
        __syncthreads();   // tile t resident everywhere; tile t-1 reads all done
        if (t + 2 < ntiles) CPKV(t + 2, (t + 2) % 3);
        CP_COMMIT();

        const uint32_t kB = sbase + (t % 3) * KVSTGW * 4;
        const uint32_t vB = kB + KTW * 4;

        const bool active = !(w < 4 && t == ntiles - 1);   // warp-uniform
        if (active) {
            // ---- S' = (Q*log2e) K^T ----
            float sacc[8][4];
            #pragma unroll
            for (int nt = 0; nt < 8; nt++)
                #pragma unroll
                for (int r = 0; r < 4; r++) sacc[nt][r] = 0.f;

            #pragma unroll
            for (int ks = 0; ks < 4; ks++) {
                #pragma unroll
                for (int g = 0; g < 4; g++) {
                    uint32_t b00, b01, b10, b11;
                    ldmx4(b00, b01, b10, b11, kB + ko[g] + ks * 32);
                    mma_f16(sacc[2 * g    ], aq[ks][0], aq[ks][1], aq[ks][2], aq[ks][3], b00, b01);
                    mma_f16(sacc[2 * g + 1], aq[ks][0], aq[ks][1], aq[ks][2], aq[ks][3], b10, b11);
                }
            }

            if (t >= ntiles - 2) {
                const int kv0 = t * 64;
                const int rel0 = q0 + w * 16 + lm - kv0;
                const int rel1 = rel0 + 8;
                #pragma unroll
                for (int nt = 0; nt < 8; nt++) {
                    const int c0 = nt * 8 + ln;
                    if (c0     > rel0) sacc[nt][0] = -1e30f;
                    if (c0 + 1 > rel0) sacc[nt][1] = -1e30f;
                    if (c0     > rel1) sacc[nt][2] = -1e30f;
                    if (c0 + 1 > rel1) sacc[nt][3] = -1e30f;
                }
            }

            float rm0 = -1e30f, rm1 = -1e30f;
            #pragma unroll
            for (int nt = 0; nt < 8; nt++) {
                rm0 = fmaxf(rm0, fmaxf(sacc[nt][0], sacc[nt][1]));
                rm1 = fmaxf(rm1, fmaxf(sacc[nt][2], sacc[nt][3]));
            }
            rm0 = fmaxf(rm0, __shfl_xor_sync(0xffffffffu, rm0, 1));
            rm0 = fmaxf(rm0, __shfl_xor_sync(0xffffffffu, rm0, 2));
            rm1 = fmaxf(rm1, __shfl_xor_sync(0xffffffffu, rm1, 1));
            rm1 = fmaxf(rm1, __shfl_xor_sync(0xffffffffu, rm1, 2));

            const float mn0 = fmaxf(m0, rm0);
            const float mn1 = fmaxf(m1, rm1);
            const float sc0 = ex2f(m0 - mn0);
            const float sc1 = ex2f(m1 - mn1);
            m0 = mn0; m1 = mn1;
            l0 *= sc0; l1 *= sc1;
            #pragma unroll
            for (int nt = 0; nt < 8; nt++) {
                oacc[nt][0] *= sc0; oacc[nt][1] *= sc0;
                oacc[nt][2] *= sc1; oacc[nt][3] *= sc1;
            }

            // ---- P = 2^(S'-m') in registers + O += P V ----
            #pragma unroll
            for (int ks = 0; ks < 4; ks++) {
                const float pe0 = ex2f(sacc[2 * ks][0] - m0);
                const float pe1 = ex2f(sacc[2 * ks][1] - m0);
                const float pe2 = ex2f(sacc[2 * ks][2] - m1);
                const float pe3 = ex2f(sacc[2 * ks][3] - m1);
                const float pf0 = ex2f(sacc[2 * ks + 1][0] - m0);
                const float pf1 = ex2f(sacc[2 * ks + 1][1] - m0);
                const float pf2 = ex2f(sacc[2 * ks + 1][2] - m1);
                const float pf3 = ex2f(sacc[2 * ks + 1][3] - m1);
                l0 += pe0 + pe1 + pf0 + pf1;
                l1 += pe2 + pe3 + pf2 + pf3;
                const uint32_t a0 = pack2(pe0, pe1);
                const uint32_t a1 = pack2(pe2, pe3);
                const uint32_t a2 = pack2(pf0, pf1);
                const uint32_t a3 = pack2(pf2, pf3);
                #pragma unroll
                for (int g = 0; g < 4; g++) {
                    uint32_t b00, b01, b10, b11;
                    ldmx4t(b00, b01, b10, b11, vB + vo[g] + ks * 16 * ASTW * 4);
                    mma_f16(oacc[2 * g    ], a0, a1, a2, a3, b00, b01);
                    mma_f16(oacc[2 * g + 1], a0, a1, a2, a3, b10, b11);
                }
            }
        }
    }

    l0 += __shfl_xor_sync(0xffffffffu, l0, 1);
    l0 += __shfl_xor_sync(0xffffffffu, l0, 2);
    l1 += __shfl_xor_sync(0xffffffffu, l1, 1);
    l1 += __shfl_xor_sync(0xffffffffu, l1, 2);
    const float inv0 = 1.f / l0;
    const float inv1 = 1.f / l1;

    uint32_t* og = (uint32_t*)g_ah +
        ((size_t)(b * SEQ + q0 + w * 16 + lm) * DMODEL + h * HDIM) / 2;
    #pragma unroll
    for (int nt = 0; nt < 8; nt++) {
        og[(nt * 8 + ln) / 2] = pack2(oacc[nt][0] * inv0, oacc[nt][1] * inv0);
        og[(8 * DMODEL + nt * 8 + ln) / 2] = pack2(oacc[nt][2] * inv1, oacc[nt][3] * inv1);
    }
}

// ---------------------------------------------------------------------------
// Launch
// ---------------------------------------------------------------------------
extern "C" void kernel_launch(void* const* d_in, const int* in_sizes, int n_in,
                              void* d_out, int out_size)
{
    (void)in_sizes; (void)n_in; (void)out_size;
    const float* x       = (const float*)d_in[0];
    const float* pos_cos = (const float*)d_in[1];
    const float* pos_sin = (const float*)d_in[2];
    const float* wq_w    = (const float*)d_in[3];
    const float* wq_b    = (const float*)d_in[4];
    const float* wk_w    = (const float*)d_in[5];
    const float* wk_b    = (const float*)d_in[6];
    const float* wv_w    = (const float*)d_in[7];
    const float* wv_b    = (const float*)d_in[8];
    const float* wo_w    = (const float*)d_in[9];
    const float* wo_b    = (const float*)d_in[10];
    float* out = (float*)d_out;

    __half *xh, *whq, *whk, *whv, *who, *qh, *kh, *vh, *ah;
    cudaGetSymbolAddress((void**)&xh,  g_xh);
    cudaGetSymbolAddress((void**)&whq, g_whq);
    cudaGetSymbolAddress((void**)&whk, g_whk);
    cudaGetSymbolAddress((void**)&whv, g_whv);
    cudaGetSymbolAddress((void**)&who, g_who);
    cudaGetSymbolAddress((void**)&qh,  g_qh);
    cudaGetSymbolAddress((void**)&kh,  g_kh);
    cudaGetSymbolAddress((void**)&vh,  g_vh);
    cudaGetSymbolAddress((void**)&ah,  g_ah);

    cudaFuncSetAttribute(gemm_f16_kernel,
                         cudaFuncAttributeMaxDynamicSharedMemorySize, SMEM_DYN);
    cudaFuncSetAttribute(attn_mma_kernel,
                         cudaFuncAttributeMaxDynamicSharedMemorySize, ATTN_SMEM);

    // merged fp32 -> fp16 conversion (Q weight pre-scaled by 0.125*log2e)
    const int X4 = MROWS * DMODEL / 4;
    const int W4 = DMODEL * DMODEL / 4;
    dim3 gc(160, 5);
    cvt_all_kernel<<<gc, 256>>>((const float4*)x, (const float4*)wq_w,
                                (const float4*)wk_w, (const float4*)wv_w,
                                (const float4*)wo_w,
                                (uint2*)xh, (uint2*)whq, (uint2*)whk,
                                (uint2*)whv, (uint2*)who, X4, W4);

    // fused QKV (Q bias also scaled by 0.125*log2e)
    dim3 gq(DMODEL / BN, MROWS / BM, 3);   // (8, 32, 3)
    gemm_f16_kernel<<<gq, 256, SMEM_DYN>>>(xh, whq, whk, whv,
                                           wq_b, wk_b, wv_b,
                                           qh, kh, vh,
                                           0.125f * LOG2E, 1, pos_cos, pos_sin, 0x3);

    dim3 ga(SEQ / 128, NHEAD, BATCH);      // (16, 16, 2)
    attn_mma_kernel<<<ga, 256, ATTN_SMEM>>>();

    // final projection
    dim3 go(DMODEL / BN, MROWS / BM, 1);
    gemm_f16_kernel<<<go, 256, SMEM_DYN>>>(ah, who, who, who,
                                           wo_b, wo_b, wo_b,
                                           out, out, out,
                                           1.0f, 0, pos_cos, pos_sin, 0);
}